// round 2
// baseline (speedup 1.0000x reference)
#include <cuda_runtime.h>

#define NA   100000
#define MM   12
#define AFD  64
#define NFD  41
#define KD   169        // 2*AFD + NFD
#define CD   128        // 2*AFD
#define NCONV 3
#define NCRY 100
#define APC  1000
#define HF   128
#define HID  64
#define EPSV 1e-5f

#define NBLK 296
#define TPB  256
#define NW   8          // warps per block

// ---------------- scratch (device globals; no allocation allowed) ----------
__device__ float g_fea0[NA * AFD];
__device__ float g_fea1[NA * AFD];
__device__ float g_summed[NA * AFD];
__device__ float g_part1[NBLK * 2 * CD];    // per-block [sum(128), sumsq(128)]
__device__ float g_part2[NBLK * 2 * AFD];   // per-block [sum(64),  sumsq(64)]
__device__ float g_sc1[CD], g_sh1[CD];      // bn1 fused scale/shift
__device__ float g_sc2[AFD], g_sh2[AFD];    // bn2 fused scale/shift

// ---------------- activations (fast-math, ~1e-6 rel err) -------------------
__device__ __forceinline__ float sigm(float x) {
    return __fdividef(1.0f, 1.0f + __expf(-x));
}
__device__ __forceinline__ float sftp(float x) {
    return fmaxf(x, 0.0f) + __logf(1.0f + __expf(-fabsf(x)));
}

// ---------------- embedding lookup -----------------------------------------
__global__ void embed_k(const int* __restrict__ an, const float* __restrict__ emb) {
    int i = blockIdx.x * blockDim.x + threadIdx.x;
    if (i < NA * AFD) {
        int n = i >> 6, c = i & 63;
        g_fea0[i] = emb[an[n] * AFD + c];
    }
}

// ---------------- fused conv pass -------------------------------------------
// PASS==1: GEMM -> per-channel sum/sumsq of gated (into g_part1)
// PASS==2: GEMM -> bn1 -> sigmoid*softplus -> sum over M -> g_summed,
//          plus per-channel sum/sumsq of summed (into g_part2)
// SMEM W is permuted: sW[k*128 + (c&31)*4 + (c>>5)] = W[k*128 + c]
// so lane L's float4 holds channels {L, L+32, L+64, L+96}.
template <int PASS>
__global__ void __launch_bounds__(TPB, 2) conv_pass(
    const float* __restrict__ afea,
    const float* __restrict__ nbrf,
    const int*   __restrict__ nidx,
    const float* __restrict__ Wl,   // KD*CD
    const float* __restrict__ bl)   // CD
{
    extern __shared__ float sW[];           // KD*CD floats (permuted)
    __shared__ float sT[NW][KD + 7];        // per-warp t row (169, padded)
    __shared__ float sred[NW][2 * CD];      // block stat reduction

    const int tid = threadIdx.x;
    const int w = tid >> 5, L = tid & 31;

    // load + permute W into SMEM
    for (int i = tid; i < KD * CD; i += TPB) {
        int k = i >> 7, c = i & 127;
        sW[(k << 7) + ((c & 31) << 2) + (c >> 5)] = Wl[i];
    }
    // bias in permuted lane order
    float b0 = bl[L], b1 = bl[32 + L], b2 = bl[64 + L], b3 = bl[96 + L];
    float sc0 = 0, sc1 = 0, sc2 = 0, sc3 = 0, sh0 = 0, sh1 = 0, sh2 = 0, sh3 = 0;
    if (PASS == 2) {
        sc0 = g_sc1[L]; sc1 = g_sc1[32 + L]; sc2 = g_sc1[64 + L]; sc3 = g_sc1[96 + L];
        sh0 = g_sh1[L]; sh1 = g_sh1[32 + L]; sh2 = g_sh1[64 + L]; sh3 = g_sh1[96 + L];
    }
    __syncthreads();

    float ls0 = 0, ls1 = 0, ls2 = 0, ls3 = 0;
    float lq0 = 0, lq1 = 0, lq2 = 0, lq3 = 0;

    float* t = sT[w];
    const float4* sW4 = (const float4*)sW;

    const int wg = blockIdx.x * NW + w;
    for (int n = wg; n < NA; n += NBLK * NW) {
        // self features (also t[0:64))
        t[L]      = afea[n * AFD + L];
        t[32 + L] = afea[n * AFD + 32 + L];

        // prefetch m = 0
        int j0 = nidx[n * MM];
        float pn0 = afea[j0 * AFD + L];
        float pn1 = afea[j0 * AFD + 32 + L];
        float pf0 = (L < NFD)      ? nbrf[(n * MM) * NFD + L]      : 0.0f;
        float pf1 = (L < NFD - 32) ? nbrf[(n * MM) * NFD + 32 + L] : 0.0f;

        float sa0 = 0, sa1 = 0;

        for (int m = 0; m < MM; m++) {
            t[64 + L] = pn0;
            t[96 + L] = pn1;
            if (L < NFD)      t[128 + L] = pf0;
            if (L < NFD - 32) t[160 + L] = pf1;
            __syncwarp();

            // prefetch m+1 under the compute
            if (m + 1 < MM) {
                int j2 = nidx[n * MM + m + 1];
                pn0 = afea[j2 * AFD + L];
                pn1 = afea[j2 * AFD + 32 + L];
                if (L < NFD)      pf0 = nbrf[(n * MM + m + 1) * NFD + L];
                if (L < NFD - 32) pf1 = nbrf[(n * MM + m + 1) * NFD + 32 + L];
            }

            float a0 = b0, a1 = b1, a2 = b2, a3 = b3;
#pragma unroll 13
            for (int k = 0; k < KD; k++) {
                float tk = t[k];
                float4 wv = sW4[(k << 5) + L];
                a0 = fmaf(tk, wv.x, a0);
                a1 = fmaf(tk, wv.y, a1);
                a2 = fmaf(tk, wv.z, a2);
                a3 = fmaf(tk, wv.w, a3);
            }

            if (PASS == 1) {
                ls0 += a0; ls1 += a1; ls2 += a2; ls3 += a3;
                lq0 = fmaf(a0, a0, lq0); lq1 = fmaf(a1, a1, lq1);
                lq2 = fmaf(a2, a2, lq2); lq3 = fmaf(a3, a3, lq3);
            } else {
                // channels: a0->L (filt), a1->L+32 (filt), a2->L+64 (core L), a3->L+96 (core L+32)
                float f0 = fmaf(a0, sc0, sh0);
                float f1 = fmaf(a1, sc1, sh1);
                float c0 = fmaf(a2, sc2, sh2);
                float c1 = fmaf(a3, sc3, sh3);
                sa0 += sigm(f0) * sftp(c0);
                sa1 += sigm(f1) * sftp(c1);
            }
            __syncwarp();   // k-loop done before next m (or next atom) rewrites t
        }

        if (PASS == 2) {
            g_summed[n * AFD + L]      = sa0;
            g_summed[n * AFD + 32 + L] = sa1;
            ls0 += sa0; ls1 += sa1;
            lq0 = fmaf(sa0, sa0, lq0);
            lq1 = fmaf(sa1, sa1, lq1);
        }
    }

    // deterministic block reduction -> per-block partials (channel-ordered)
    if (PASS == 1) {
        sred[w][L]       = ls0; sred[w][32 + L]  = ls1;
        sred[w][64 + L]  = ls2; sred[w][96 + L]  = ls3;
        sred[w][128 + L] = lq0; sred[w][160 + L] = lq1;
        sred[w][192 + L] = lq2; sred[w][224 + L] = lq3;
        __syncthreads();
        float s = 0;
#pragma unroll
        for (int ww = 0; ww < NW; ww++) s += sred[ww][tid];
        g_part1[blockIdx.x * 2 * CD + tid] = s;
    } else {
        sred[w][L]      = ls0; sred[w][32 + L] = ls1;
        sred[w][64 + L] = lq0; sred[w][96 + L] = lq1;
        __syncthreads();
        if (tid < 2 * AFD) {
            float s = 0;
#pragma unroll
            for (int ww = 0; ww < NW; ww++) s += sred[ww][tid];
            g_part2[blockIdx.x * 2 * AFD + tid] = s;
        }
    }
}

// ---------------- BN finalize (deterministic sums over block partials) ------
__global__ void fin1_k(const float* __restrict__ g, const float* __restrict__ b) {
    int c = threadIdx.x;  // 128
    float s = 0, q = 0;
    for (int bl = 0; bl < NBLK; bl++) {
        s += g_part1[bl * 2 * CD + c];
        q += g_part1[bl * 2 * CD + CD + c];
    }
    const float inv = 1.0f / ((float)NA * (float)MM);
    float mu = s * inv;
    float var = q * inv - mu * mu;
    float rs = rsqrtf(var + EPSV);
    float sc = g[c] * rs;
    g_sc1[c] = sc;
    g_sh1[c] = b[c] - mu * sc;
}

__global__ void fin2_k(const float* __restrict__ g, const float* __restrict__ b) {
    int c = threadIdx.x;  // 64
    float s = 0, q = 0;
    for (int bl = 0; bl < NBLK; bl++) {
        s += g_part2[bl * 2 * AFD + c];
        q += g_part2[bl * 2 * AFD + AFD + c];
    }
    const float inv = 1.0f / (float)NA;
    float mu = s * inv;
    float var = q * inv - mu * mu;
    float rs = rsqrtf(var + EPSV);
    float sc = g[c] * rs;
    g_sc2[c] = sc;
    g_sh2[c] = b[c] - mu * sc;
}

// ---------------- residual + bn2 + softplus ---------------------------------
__global__ void update_k(const float* __restrict__ fin, float* __restrict__ fout) {
    int i = blockIdx.x * blockDim.x + threadIdx.x;
    if (i < NA * AFD) {
        int c = i & 63;
        float v = fin[i] + fmaf(g_summed[i], g_sc2[c], g_sh2[c]);
        fout[i] = sftp(v);
    }
}

// ---------------- head: pool + softplus + FC + softplus + FC ----------------
__global__ void head_k(const float* __restrict__ afea, const int* __restrict__ cai,
                       const float* __restrict__ Wfc, const float* __restrict__ bfc,
                       const float* __restrict__ Wout, const float* __restrict__ bout,
                       float* __restrict__ out) {
    __shared__ float scry[AFD];
    __shared__ float shid[HF];
    __shared__ float part[2][AFD];
    int b = blockIdx.x, t = threadIdx.x;  // 128 threads
    int c = t & 63, h = t >> 6;

    const int* idx = cai + b * APC;
    float acc = 0;
    for (int a = h * (APC / 2); a < (h + 1) * (APC / 2); a++)
        acc += afea[idx[a] * AFD + c];
    part[h][c] = acc;
    __syncthreads();

    if (t < AFD) {
        float mval = (part[0][t] + part[1][t]) * (1.0f / (float)APC);
        scry[t] = sftp(mval);
    }
    __syncthreads();

    float a2 = bfc[t];
    for (int k = 0; k < AFD; k++) a2 = fmaf(scry[k], Wfc[k * HF + t], a2);
    shid[t] = sftp(a2);
    __syncthreads();

    if (t < HID) {
        float a3 = bout[t];
        for (int k = 0; k < HF; k++) a3 = fmaf(shid[k], Wout[k * HID + t], a3);
        out[b * HID + t] = a3;
    }
}

// ---------------- launch ----------------------------------------------------
extern "C" void kernel_launch(void* const* d_in, const int* in_sizes, int n_in,
                              void* d_out, int out_size) {
    const int*   atom_num = (const int*)d_in[0];
    const float* nbr_fea  = (const float*)d_in[1];
    const int*   nidx     = (const int*)d_in[2];
    const int*   cai      = (const int*)d_in[3];
    const float* emb      = (const float*)d_in[4];
    const float* W_full   = (const float*)d_in[5];
    const float* b_full   = (const float*)d_in[6];
    const float* bn1g     = (const float*)d_in[7];
    const float* bn1b     = (const float*)d_in[8];
    const float* bn2g     = (const float*)d_in[9];
    const float* bn2b     = (const float*)d_in[10];
    const float* Wfc      = (const float*)d_in[11];
    const float* bfc      = (const float*)d_in[12];
    const float* Wout     = (const float*)d_in[13];
    const float* bout     = (const float*)d_in[14];
    float* out = (float*)d_out;

    const int smem = KD * CD * (int)sizeof(float);  // 86528
    cudaFuncSetAttribute(conv_pass<1>, cudaFuncAttributeMaxDynamicSharedMemorySize, smem);
    cudaFuncSetAttribute(conv_pass<2>, cudaFuncAttributeMaxDynamicSharedMemorySize, smem);

    void *p0, *p1;
    cudaGetSymbolAddress(&p0, g_fea0);
    cudaGetSymbolAddress(&p1, g_fea1);
    float* fin  = (float*)p0;
    float* fout = (float*)p1;

    embed_k<<<(NA * AFD + TPB - 1) / TPB, TPB>>>(atom_num, emb);

    for (int i = 0; i < NCONV; i++) {
        const float* Wl = W_full + (size_t)i * KD * CD;
        const float* bl = b_full + (size_t)i * CD;
        conv_pass<1><<<NBLK, TPB, smem>>>(fin, nbr_fea, nidx, Wl, bl);
        fin1_k<<<1, CD>>>(bn1g + (size_t)i * CD, bn1b + (size_t)i * CD);
        conv_pass<2><<<NBLK, TPB, smem>>>(fin, nbr_fea, nidx, Wl, bl);
        fin2_k<<<1, AFD>>>(bn2g + (size_t)i * AFD, bn2b + (size_t)i * AFD);
        update_k<<<(NA * AFD + TPB - 1) / TPB, TPB>>>(fin, fout);
        float* tmp = fin; fin = fout; fout = tmp;
    }

    head_k<<<NCRY, 128>>>(fin, cai, Wfc, bfc, Wout, bout, out);
}

// round 6
// speedup vs baseline: 2.2399x; 2.2399x over previous
#include <cuda_runtime.h>

#define NA   100000
#define MM   12
#define AFD  64
#define NFD  41
#define KD   169        // 2*AFD + NFD
#define CD   128        // 2*AFD
#define NCONV 3
#define NCRY 100
#define APC  1000
#define HF   128
#define HID  64
#define EPSV 1e-5f

#define NBLK   148
#define TATOMS 10
#define NTILES (NA / TATOMS)     // 10000
#define TROWS  (TATOMS * MM)     // 120
#define ASTR   132               // padded row stride of transposed A tile (floats)
#define ABSTR  68                // activation buffer stride

// smem layout (in floats)
#define AS_OFF  (KD * CD)                 // Bs: [0, 21632)
#define IDX_OFF (AS_OFF + KD * ASTR)      // As: [21632, 43940)
#define SMEMF   (IDX_OFF + 128)
#define SMEMB   (SMEMF * 4)

typedef unsigned long long ull;

// ---------------- scratch (device globals; no allocation allowed) ----------
__device__ float g_fea0[NA * AFD];
__device__ float g_fea1[NA * AFD];
__device__ float g_summed[NA * AFD];
__device__ float g_part1[NBLK * 2 * CD];
__device__ float g_part2[NBLK * 2 * AFD];
__device__ float g_sc1[CD], g_sh1[CD];
__device__ float g_sc2[AFD], g_sh2[AFD];

// ---------------- packed f32x2 helpers --------------------------------------
__device__ __forceinline__ ull dup2(float x) {
    ull r; asm("mov.b64 %0,{%1,%1};" : "=l"(r) : "f"(x)); return r;
}
__device__ __forceinline__ ull pack2(float x, float y) {
    ull r; asm("mov.b64 %0,{%1,%2};" : "=l"(r) : "f"(x), "f"(y)); return r;
}
__device__ __forceinline__ float2 unpk(ull v) {
    float2 r; asm("mov.b64 {%0,%1},%2;" : "=f"(r.x), "=f"(r.y) : "l"(v)); return r;
}
#define FMA2(d, a, b) asm("fma.rn.f32x2 %0,%1,%2,%0;" : "+l"(d) : "l"(a), "l"(b))
#define ADD2(d, a)    asm("add.rn.f32x2 %0,%1,%0;"    : "+l"(d) : "l"(a))

// ---------------- activations ------------------------------------------------
__device__ __forceinline__ float sigm(float x) {
    return __fdividef(1.0f, 1.0f + __expf(-x));
}
__device__ __forceinline__ float sftp(float x) {
    return fmaxf(x, 0.0f) + __logf(1.0f + __expf(-fabsf(x)));
}

// ---------------- embedding lookup -------------------------------------------
__global__ void embed_k(const int* __restrict__ an, const float* __restrict__ emb) {
    int i = blockIdx.x * blockDim.x + threadIdx.x;
    if (i < NA * AFD) {
        int n = i >> 6, c = i & 63;
        g_fea0[i] = emb[an[n] * AFD + c];
    }
}

// ---------------- register-tiled GEMM conv pass ------------------------------
// Tile: 128 rows (10 atoms x 12 nbrs + 8 zero pad) x 128 channels, K=169.
// 512 threads; thread (tx,ty): rows r0..r0+3, channels {c0..c0+3, 64+c0..64+c0+3}.
// PASS1: per-channel sum/sumsq of gated -> g_part1 (register-accumulated)
// PASS2: bn1 -> sigmoid*softplus -> 12-row segment sum -> g_summed (+ stats)
template <int PASS>
__global__ void __launch_bounds__(512, 1) conv2(
    const float* __restrict__ afea,
    const float* __restrict__ nbrf,
    const int*   __restrict__ nidx,
    const float* __restrict__ Wl,
    const float* __restrict__ bl)
{
    extern __shared__ float sm[];
    float* Bs   = sm;                 // W: [k][c], 169x128
    float* As   = sm + AS_OFF;        // t^T: [k][r], 169x132 (padded)
    int*   sIdx = (int*)(sm + IDX_OFF);

    const int tid = threadIdx.x;
    const int tx = tid & 15, ty = tid >> 4;
    const int c0 = tx * 4, r0 = ty * 4;

    // W resident in SMEM for whole kernel
    for (int i = tid; i < KD * CD; i += 512) Bs[i] = Wl[i];
    // zero pad rows 120..127 once (staging never touches them)
    for (int i = tid; i < KD * 8; i += 512) As[(i >> 3) * ASTR + TROWS + (i & 7)] = 0.0f;

    const ull b00 = pack2(bl[c0],     bl[c0 + 1]);
    const ull b01 = pack2(bl[c0 + 2], bl[c0 + 3]);
    const ull b10 = pack2(bl[64 + c0],     bl[64 + c0 + 1]);
    const ull b11 = pack2(bl[64 + c0 + 2], bl[64 + c0 + 3]);

    float scF[4], shF[4], scC[4], shC[4];
    if (PASS == 2) {
#pragma unroll
        for (int j = 0; j < 4; j++) {
            scF[j] = g_sc1[c0 + j];      shF[j] = g_sh1[c0 + j];
            scC[j] = g_sc1[64 + c0 + j]; shC[j] = g_sh1[64 + c0 + j];
        }
    }

    ull fs2[4], fq2[4];
    float ssum = 0.0f, ssq = 0.0f;
    if (PASS == 1) {
#pragma unroll
        for (int j = 0; j < 4; j++) { fs2[j] = 0ull; fq2[j] = 0ull; }
    }

    for (int tile = blockIdx.x; tile < NTILES; tile += NBLK) {
        const int n0 = tile * TATOMS;
        __syncthreads();   // previous tile's reads of As done before restage

        if (tid < TROWS) sIdx[tid] = nidx[n0 * MM + tid];

        // self features: As[k][a*12+m] = afea[n0+a][k], replicated across m
        for (int idx = tid; idx < TATOMS * AFD; idx += 512) {
            int a = idx >> 6, k = idx & 63;
            float v = afea[(n0 + a) * AFD + k];
            float* p = &As[k * ASTR + a * MM];
#pragma unroll
            for (int m = 0; m < MM; m++) p[m] = v;
        }
        __syncthreads();   // sIdx ready

        // neighbor features (gather)
        for (int idx = tid; idx < TROWS * AFD; idx += 512) {
            int r = idx >> 6, k = idx & 63;
            As[(AFD + k) * ASTR + r] = afea[sIdx[r] * AFD + k];
        }
        // bond features
        for (int idx = tid; idx < TROWS * NFD; idx += 512) {
            int r = idx / NFD, k = idx - r * NFD;
            As[(2 * AFD + k) * ASTR + r] = nbrf[(n0 * MM + r) * NFD + k];
        }
        __syncthreads();

        // ---- GEMM: acc[i][j] = row (r0+i), channel-pairs {c0,c0+2,64+c0,64+c0+2}
        ull acc[4][4];
#pragma unroll
        for (int i = 0; i < 4; i++) {
            acc[i][0] = b00; acc[i][1] = b01; acc[i][2] = b10; acc[i][3] = b11;
        }

        const float* ap  = &As[r0];
        const float* bp0 = &Bs[c0];
        const float* bp1 = &Bs[64 + c0];
#pragma unroll 13
        for (int k = 0; k < KD; k++) {
            float4 av = *(const float4*)(ap + k * ASTR);
            ulonglong2 bv0 = *(const ulonglong2*)(bp0 + k * CD);
            ulonglong2 bv1 = *(const ulonglong2*)(bp1 + k * CD);
            ull a0 = dup2(av.x), a1 = dup2(av.y), a2 = dup2(av.z), a3 = dup2(av.w);
            FMA2(acc[0][0], a0, bv0.x); FMA2(acc[0][1], a0, bv0.y);
            FMA2(acc[0][2], a0, bv1.x); FMA2(acc[0][3], a0, bv1.y);
            FMA2(acc[1][0], a1, bv0.x); FMA2(acc[1][1], a1, bv0.y);
            FMA2(acc[1][2], a1, bv1.x); FMA2(acc[1][3], a1, bv1.y);
            FMA2(acc[2][0], a2, bv0.x); FMA2(acc[2][1], a2, bv0.y);
            FMA2(acc[2][2], a2, bv1.x); FMA2(acc[2][3], a2, bv1.y);
            FMA2(acc[3][0], a3, bv0.x); FMA2(acc[3][1], a3, bv0.y);
            FMA2(acc[3][2], a3, bv1.x); FMA2(acc[3][3], a3, bv1.y);
        }

        if (PASS == 1) {
            // rows r0..r0+3 valid iff < 120  ->  ty < 30
            if (ty < 30) {
#pragma unroll
                for (int i = 0; i < 4; i++)
#pragma unroll
                    for (int j = 0; j < 4; j++) {
                        ADD2(fs2[j], acc[i][j]);
                        FMA2(fq2[j], acc[i][j], acc[i][j]);
                    }
            }
        } else {
            __syncthreads();            // all GEMM reads of As done before reuse
            float* aBuf = As;           // [128][ABSTR]
#pragma unroll
            for (int i = 0; i < 4; i++) {
                float2 f0 = unpk(acc[i][0]), f1 = unpk(acc[i][1]);
                float2 q0 = unpk(acc[i][2]), q1 = unpk(acc[i][3]);
                float f[4] = {f0.x, f0.y, f1.x, f1.y};
                float q[4] = {q0.x, q0.y, q1.x, q1.y};
                float4 o;
                float* op = (float*)&o;
#pragma unroll
                for (int j = 0; j < 4; j++) {
                    float fb = fmaf(f[j], scF[j], shF[j]);
                    float cb = fmaf(q[j], scC[j], shC[j]);
                    op[j] = sigm(fb) * sftp(cb);
                }
                *(float4*)&aBuf[(r0 + i) * ABSTR + c0] = o;
            }
            __syncthreads();
            for (int o = tid; o < TATOMS * AFD; o += 512) {
                int a = o >> 6, c = o & 63;
                float s = 0.0f;
#pragma unroll
                for (int m = 0; m < MM; m++) s += aBuf[(a * MM + m) * ABSTR + c];
                g_summed[(n0 + a) * AFD + c] = s;
                ssum += s; ssq = fmaf(s, s, ssq);
            }
        }
    }

    // ---- deterministic block-level stat reduction (reuse As) ----
    __syncthreads();
    float* sR = As;
    if (PASS == 1) {
#pragma unroll
        for (int j = 0; j < 4; j++) {
            float2 s = unpk(fs2[j]), q = unpk(fq2[j]);
            sR[tid * 16 + j * 2]         = s.x;
            sR[tid * 16 + j * 2 + 1]     = s.y;
            sR[tid * 16 + 8 + j * 2]     = q.x;
            sR[tid * 16 + 8 + j * 2 + 1] = q.y;
        }
        __syncthreads();
        if (tid < 256) {
            int stat = tid >> 7, c = tid & 127;
            int txx = (c & 63) >> 2, pos = (c >> 6) * 4 + (c & 3);
            float v = 0.0f;
            for (int tyy = 0; tyy < 32; tyy++)
                v += sR[(tyy * 16 + txx) * 16 + stat * 8 + pos];
            g_part1[blockIdx.x * 2 * CD + tid] = v;
        }
    } else {
        sR[tid * 2]     = ssum;
        sR[tid * 2 + 1] = ssq;
        __syncthreads();
        if (tid < 128) {
            int stat = tid >> 6, c = tid & 63;
            float v = 0.0f;
            for (int g = 0; g < 8; g++) v += sR[(g * 64 + c) * 2 + stat];
            g_part2[blockIdx.x * 2 * AFD + tid] = v;
        }
    }
}

// ---------------- BN finalize -------------------------------------------------
__global__ void fin1_k(const float* __restrict__ g, const float* __restrict__ b) {
    int c = threadIdx.x;  // 128
    float s = 0, q = 0;
    for (int bl = 0; bl < NBLK; bl++) {
        s += g_part1[bl * 2 * CD + c];
        q += g_part1[bl * 2 * CD + CD + c];
    }
    const float inv = 1.0f / ((float)NA * (float)MM);
    float mu = s * inv;
    float var = q * inv - mu * mu;
    float rs = rsqrtf(var + EPSV);
    float sc = g[c] * rs;
    g_sc1[c] = sc;
    g_sh1[c] = b[c] - mu * sc;
}

__global__ void fin2_k(const float* __restrict__ g, const float* __restrict__ b) {
    int c = threadIdx.x;  // 64
    float s = 0, q = 0;
    for (int bl = 0; bl < NBLK; bl++) {
        s += g_part2[bl * 2 * AFD + c];
        q += g_part2[bl * 2 * AFD + AFD + c];
    }
    const float inv = 1.0f / (float)NA;
    float mu = s * inv;
    float var = q * inv - mu * mu;
    float rs = rsqrtf(var + EPSV);
    float sc = g[c] * rs;
    g_sc2[c] = sc;
    g_sh2[c] = b[c] - mu * sc;
}

// ---------------- residual + bn2 + softplus ----------------------------------
__global__ void update_k(const float* __restrict__ fin, float* __restrict__ fout) {
    int i = blockIdx.x * blockDim.x + threadIdx.x;
    if (i < NA * AFD) {
        int c = i & 63;
        float v = fin[i] + fmaf(g_summed[i], g_sc2[c], g_sh2[c]);
        fout[i] = sftp(v);
    }
}

// ---------------- head -------------------------------------------------------
__global__ void head_k(const float* __restrict__ afea, const int* __restrict__ cai,
                       const float* __restrict__ Wfc, const float* __restrict__ bfc,
                       const float* __restrict__ Wout, const float* __restrict__ bout,
                       float* __restrict__ out) {
    __shared__ float scry[AFD];
    __shared__ float shid[HF];
    __shared__ float part[2][AFD];
    int b = blockIdx.x, t = threadIdx.x;  // 128 threads
    int c = t & 63, h = t >> 6;

    const int* idx = cai + b * APC;
    float acc = 0;
    for (int a = h * (APC / 2); a < (h + 1) * (APC / 2); a++)
        acc += afea[idx[a] * AFD + c];
    part[h][c] = acc;
    __syncthreads();

    if (t < AFD) {
        float mval = (part[0][t] + part[1][t]) * (1.0f / (float)APC);
        scry[t] = sftp(mval);
    }
    __syncthreads();

    float a2 = bfc[t];
    for (int k = 0; k < AFD; k++) a2 = fmaf(scry[k], Wfc[k * HF + t], a2);
    shid[t] = sftp(a2);
    __syncthreads();

    if (t < HID) {
        float a3 = bout[t];
        for (int k = 0; k < HF; k++) a3 = fmaf(shid[k], Wout[k * HID + t], a3);
        out[b * HID + t] = a3;
    }
}

// ---------------- launch -----------------------------------------------------
extern "C" void kernel_launch(void* const* d_in, const int* in_sizes, int n_in,
                              void* d_out, int out_size) {
    const int*   atom_num = (const int*)d_in[0];
    const float* nbr_fea  = (const float*)d_in[1];
    const int*   nidx     = (const int*)d_in[2];
    const int*   cai      = (const int*)d_in[3];
    const float* emb      = (const float*)d_in[4];
    const float* W_full   = (const float*)d_in[5];
    const float* b_full   = (const float*)d_in[6];
    const float* bn1g     = (const float*)d_in[7];
    const float* bn1b     = (const float*)d_in[8];
    const float* bn2g     = (const float*)d_in[9];
    const float* bn2b     = (const float*)d_in[10];
    const float* Wfc      = (const float*)d_in[11];
    const float* bfc      = (const float*)d_in[12];
    const float* Wout     = (const float*)d_in[13];
    const float* bout     = (const float*)d_in[14];
    float* out = (float*)d_out;

    cudaFuncSetAttribute(conv2<1>, cudaFuncAttributeMaxDynamicSharedMemorySize, SMEMB);
    cudaFuncSetAttribute(conv2<2>, cudaFuncAttributeMaxDynamicSharedMemorySize, SMEMB);

    void *p0, *p1;
    cudaGetSymbolAddress(&p0, g_fea0);
    cudaGetSymbolAddress(&p1, g_fea1);
    float* fin  = (float*)p0;
    float* fout = (float*)p1;

    embed_k<<<(NA * AFD + 255) / 256, 256>>>(atom_num, emb);

    for (int i = 0; i < NCONV; i++) {
        const float* Wl = W_full + (size_t)i * KD * CD;
        const float* bl = b_full + (size_t)i * CD;
        conv2<1><<<NBLK, 512, SMEMB>>>(fin, nbr_fea, nidx, Wl, bl);
        fin1_k<<<1, CD>>>(bn1g + (size_t)i * CD, bn1b + (size_t)i * CD);
        conv2<2><<<NBLK, 512, SMEMB>>>(fin, nbr_fea, nidx, Wl, bl);
        fin2_k<<<1, AFD>>>(bn2g + (size_t)i * AFD, bn2b + (size_t)i * AFD);
        update_k<<<(NA * AFD + 255) / 256, 256>>>(fin, fout);
        float* tmp = fin; fin = fout; fout = tmp;
    }

    head_k<<<NCRY, 128>>>(fin, cai, Wfc, bfc, Wout, bout, out);
}

// round 9
// speedup vs baseline: 3.7613x; 1.6792x over previous
#include <cuda_runtime.h>
#include <cuda_bf16.h>
#include <cstdint>

#define NA   100000
#define MM   12
#define AFD  64
#define NFD  41
#define KD   169
#define CD   128
#define NCONV 3
#define NCRY 100
#define APC  1000
#define HF   128
#define HID  64
#define EPSV 1e-5f

#define NBLK   148
#define TATOMS 10
#define NTILES (NA / TATOMS)     // 10000
#define TROWS  (TATOMS * MM)     // 120
#define KSTEPS 11                // K = 176 (169 + zero pad)

#define ASTRE 184                // bf16 elems per row (padded, conflict-free LDSM)
#define ASTRB 368                // bytes per row

// ---- SMEM byte offsets (relative to 1024-aligned base) ----
#define AHI_OFF   0u
#define ALO_OFF   47104u         // 128*184*2
#define WHI_OFF   94208u
#define WLO_OFF   141312u
#define BIAS_OFF  188416u        // 128 f32
#define SC_OFF    188928u
#define SH_OFF    189440u
#define IDX_OFF   189952u        // 120 i32
#define SMEM_USED 190464u
#define SMEM_DYN  (SMEM_USED + 1024u)

#define BUFSTR 132               // PASS2 f32 epilogue buffer stride

typedef unsigned long long ull;

// ---------------- scratch (device globals) ----------------------------------
__device__ float g_fea0[NA * AFD];
__device__ float g_fea1[NA * AFD];
__device__ float g_summed[NA * AFD];
__device__ float g_part1[NBLK * 2 * CD];
__device__ float g_part2[NBLK * 2 * AFD];
__device__ float g_sc1[CD], g_sh1[CD];
__device__ float g_sc2[AFD], g_sh2[AFD];

// ---------------- helpers ----------------------------------------------------
__device__ __forceinline__ uint32_t smem_u32(const void* p) {
    uint32_t a;
    asm("{ .reg .u64 t; cvta.to.shared.u64 t, %1; cvt.u32.u64 %0, t; }"
        : "=r"(a) : "l"(p));
    return a;
}

#define LDSM4(r, addr) \
    asm volatile("ldmatrix.sync.aligned.m8n8.x4.shared.b16 {%0,%1,%2,%3},[%4];" \
        : "=r"((r)[0]), "=r"((r)[1]), "=r"((r)[2]), "=r"((r)[3]) : "r"(addr))

#define MMA16(c, a, b) \
    asm volatile("mma.sync.aligned.m16n8k16.row.col.f32.bf16.bf16.f32 " \
        "{%0,%1,%2,%3},{%4,%5,%6,%7},{%8,%9},{%0,%1,%2,%3};" \
        : "+f"((c)[0]), "+f"((c)[1]), "+f"((c)[2]), "+f"((c)[3]) \
        : "r"((a)[0]), "r"((a)[1]), "r"((a)[2]), "r"((a)[3]), \
          "r"((b)[0]), "r"((b)[1]))

__device__ __forceinline__ void stbf2(char* AHI, char* ALO, uint32_t off, float v) {
    __nv_bfloat16 h = __float2bfloat16(v);
    float lo = v - __bfloat162float(h);
    *(__nv_bfloat16*)(AHI + off) = h;
    *(__nv_bfloat16*)(ALO + off) = __float2bfloat16(lo);
}

__device__ __forceinline__ float sigm(float x) {
    return __fdividef(1.0f, 1.0f + __expf(-x));
}
__device__ __forceinline__ float sftp(float x) {
    return fmaxf(x, 0.0f) + __logf(1.0f + __expf(-fabsf(x)));
}

// ---------------- embedding --------------------------------------------------
__global__ void embed_k(const int* __restrict__ an, const float* __restrict__ emb) {
    int i = blockIdx.x * blockDim.x + threadIdx.x;
    if (i < NA * AFD) {
        int n = i >> 6, c = i & 63;
        g_fea0[i] = emb[an[n] * AFD + c];
    }
}

// ---------------- HMMA (mma.sync bf16 split hi/lo) conv pass ------------------
// Tile: 128 rows (10 atoms x 12 nbrs + 8 pad) x 128 ch, K=176 (169 + pad).
// 16 warps: warp_m = wid&3 (32 rows), warp_n = wid>>2 (32 cols).
// D = Ah*Wh + Ah*Wl + Al*Wh  in fp32 accumulators.
template <int PASS>
__global__ void __launch_bounds__(512, 1) conv4(
    const float* __restrict__ afea,
    const float* __restrict__ nbrf,
    const int*   __restrict__ nidx,
    const float* __restrict__ Wl,
    const float* __restrict__ bl)
{
    extern __shared__ char smraw[];
    char* base = (char*)((((uintptr_t)smraw) + 1023) & ~(uintptr_t)1023);
    const uint32_t bu = smem_u32(base);

    char* AHI = base + AHI_OFF;
    char* ALO = base + ALO_OFF;
    char* WHI = base + WHI_OFF;
    char* WLO = base + WLO_OFF;
    float* biasS = (float*)(base + BIAS_OFF);
    float* scS   = (float*)(base + SC_OFF);
    float* shS   = (float*)(base + SH_OFF);
    int*   sIdx  = (int*)(base + IDX_OFF);

    const int tid = threadIdx.x, wid = tid >> 5, lane = tid & 31;
    const int warp_m = wid & 3, warp_n = wid >> 2;
    const int R0 = warp_m * 32, N0 = warp_n * 32;

    // zero the whole A+W region once (pads stay zero; PASS2 re-zeros clobbered pads)
    for (int i = tid; i < (int)(188416 / 4); i += 512) ((uint32_t*)base)[i] = 0;
    if (tid < 128) {
        biasS[tid] = bl[tid];
        if (PASS == 2) { scS[tid] = g_sc1[tid]; shS[tid] = g_sh1[tid]; }
    }
    __syncthreads();

    // stage W^T hi/lo once: Wt[c][k]
    for (int i = tid; i < KD * CD; i += 512) {
        int k = i >> 7, c = i & 127;
        stbf2(WHI, WLO, (uint32_t)((c * ASTRE + k) * 2), Wl[i]);
    }

    // ldmatrix lane addresses (canonical recipes)
    // A (row-major m16k16, x4): &A[R + lane%16][(lane/16)*8]
    const uint32_t aOff = (uint32_t)(((R0 + (lane & 15)) * ASTRE + (lane >> 4) * 8) * 2);
    const uint32_t aH0 = bu + AHI_OFF + aOff;
    const uint32_t aH1 = aH0 + 16 * ASTRB;
    const uint32_t aL0 = bu + ALO_OFF + aOff;
    const uint32_t aL1 = aL0 + 16 * ASTRB;
    // B (two n-tiles per x4): &Wt[n0 + lane%8 + (lane/16)*8][((lane>>3)&1)*8]
    const uint32_t bOff = (uint32_t)(((N0 + (lane & 7) + (lane >> 4) * 8) * ASTRE
                                      + ((lane >> 3) & 1) * 8) * 2);
    const uint32_t bH0 = bu + WHI_OFF + bOff;       // ntiles 0,1
    const uint32_t bH1 = bH0 + 16 * ASTRB;          // ntiles 2,3
    const uint32_t bL0 = bu + WLO_OFF + bOff;
    const uint32_t bL1 = bL0 + 16 * ASTRB;

    // per-thread bias for its 8 channels: col = N0 + j*8 + (lane&3)*2 + e
    float bch[8];
#pragma unroll
    for (int j = 0; j < 4; j++) {
        bch[j * 2 + 0] = biasS[N0 + j * 8 + (lane & 3) * 2];
        bch[j * 2 + 1] = biasS[N0 + j * 8 + (lane & 3) * 2 + 1];
    }

    float sS[8], sQ[8];
#pragma unroll
    for (int j = 0; j < 8; j++) { sS[j] = 0.0f; sQ[j] = 0.0f; }
    float ssum = 0.0f, ssq = 0.0f;

    for (int tile = blockIdx.x; tile < NTILES; tile += NBLK) {
        const int n0 = tile * TATOMS;
        __syncthreads();   // prior tile fully consumed (mma reads / buf reads)

        if (PASS == 2) {
            // re-zero pads clobbered by last tile's f32 epilogue buffer
            for (int i = tid; i < 8 * 92; i += 512) {
                ((uint32_t*)(AHI + 120 * ASTRB))[i] = 0;
                ((uint32_t*)(ALO + 120 * ASTRB))[i] = 0;
            }
            for (int i = tid; i < TROWS * 7; i += 512) {
                int r = i / 7, k = 169 + (i - r * 7);
                *(__nv_bfloat16*)(AHI + r * ASTRB + k * 2) = __nv_bfloat16(0.f);
                *(__nv_bfloat16*)(ALO + r * ASTRB + k * 2) = __nv_bfloat16(0.f);
            }
        }
        if (tid < TROWS) sIdx[tid] = nidx[n0 * MM + tid];

        // self features, replicated over the 12 neighbor rows
        for (int i = tid; i < TATOMS * AFD; i += 512) {
            int a = i >> 6, k = i & 63;
            float v = afea[(n0 + a) * AFD + k];
            __nv_bfloat16 h = __float2bfloat16(v);
            __nv_bfloat16 l = __float2bfloat16(v - __bfloat162float(h));
            uint32_t o = (uint32_t)((a * MM * ASTRE + k) * 2);
#pragma unroll
            for (int m = 0; m < MM; m++) {
                *(__nv_bfloat16*)(AHI + o) = h;
                *(__nv_bfloat16*)(ALO + o) = l;
                o += ASTRB;
            }
        }
        __syncthreads();   // sIdx ready (and pad zeroing done)

        for (int i = tid; i < TROWS * AFD; i += 512) {       // neighbor gather
            int r = i >> 6, k = i & 63;
            stbf2(AHI, ALO, (uint32_t)((r * ASTRE + AFD + k) * 2),
                  afea[sIdx[r] * AFD + k]);
        }
        for (int i = tid; i < TROWS * NFD; i += 512) {       // bond features
            int r = i / NFD, k = i - r * NFD;
            stbf2(AHI, ALO, (uint32_t)((r * ASTRE + 2 * AFD + k) * 2),
                  nbrf[(n0 * MM + r) * NFD + k]);
        }
        __syncthreads();

        // ---- GEMM ----
        float C[2][4][4];
#pragma unroll
        for (int mi = 0; mi < 2; mi++)
#pragma unroll
            for (int j = 0; j < 4; j++)
#pragma unroll
                for (int p = 0; p < 4; p++) C[mi][j][p] = 0.0f;

#pragma unroll
        for (int ks = 0; ks < KSTEPS; ks++) {
            const uint32_t ko = (uint32_t)ks * 32u;
            uint32_t ah0[4], ah1[4], wh0[4], wh1[4], wl0[4], wl1[4], al0[4], al1[4];
            LDSM4(ah0, aH0 + ko); LDSM4(ah1, aH1 + ko);
            LDSM4(wh0, bH0 + ko); LDSM4(wh1, bH1 + ko);
            MMA16(C[0][0], ah0, wh0 + 0); MMA16(C[0][1], ah0, wh0 + 2);
            MMA16(C[0][2], ah0, wh1 + 0); MMA16(C[0][3], ah0, wh1 + 2);
            MMA16(C[1][0], ah1, wh0 + 0); MMA16(C[1][1], ah1, wh0 + 2);
            MMA16(C[1][2], ah1, wh1 + 0); MMA16(C[1][3], ah1, wh1 + 2);
            LDSM4(wl0, bL0 + ko); LDSM4(wl1, bL1 + ko);
            MMA16(C[0][0], ah0, wl0 + 0); MMA16(C[0][1], ah0, wl0 + 2);
            MMA16(C[0][2], ah0, wl1 + 0); MMA16(C[0][3], ah0, wl1 + 2);
            MMA16(C[1][0], ah1, wl0 + 0); MMA16(C[1][1], ah1, wl0 + 2);
            MMA16(C[1][2], ah1, wl1 + 0); MMA16(C[1][3], ah1, wl1 + 2);
            LDSM4(al0, aL0 + ko); LDSM4(al1, aL1 + ko);
            MMA16(C[0][0], al0, wh0 + 0); MMA16(C[0][1], al0, wh0 + 2);
            MMA16(C[0][2], al0, wh1 + 0); MMA16(C[0][3], al0, wh1 + 2);
            MMA16(C[1][0], al1, wh0 + 0); MMA16(C[1][1], al1, wh0 + 2);
            MMA16(C[1][2], al1, wh1 + 0); MMA16(C[1][3], al1, wh1 + 2);
        }

        if (PASS == 1) {
            // register-resident BN stats; rows 120-127 (warp_m==3, mi==1, p>=2) masked
#pragma unroll
            for (int mi = 0; mi < 2; mi++) {
                const bool bad = (warp_m == 3) && (mi == 1);
#pragma unroll
                for (int j = 0; j < 4; j++)
#pragma unroll
                    for (int p = 0; p < 4; p++) {
                        if (bad && p >= 2) continue;
                        float v = C[mi][j][p] + bch[j * 2 + (p & 1)];
                        sS[j * 2 + (p & 1)] += v;
                        sQ[j * 2 + (p & 1)] = fmaf(v, v, sQ[j * 2 + (p & 1)]);
                    }
            }
        } else {
            __syncthreads();               // all warps done reading A before reuse
            float* buf = (float*)base;     // f32 [128][BUFSTR], overlays A region
#pragma unroll
            for (int mi = 0; mi < 2; mi++)
#pragma unroll
                for (int j = 0; j < 4; j++)
#pragma unroll
                    for (int p = 0; p < 4; p++) {
                        int row = R0 + mi * 16 + (lane >> 2) + (p >> 1) * 8;
                        int col = N0 + j * 8 + (lane & 3) * 2 + (p & 1);
                        buf[row * BUFSTR + col] = C[mi][j][p] + bch[j * 2 + (p & 1)];
                    }
            __syncthreads();
            // bn1 -> sigmoid*softplus -> 12-row sums (all fp32)
            for (int o = tid; o < TATOMS * AFD; o += 512) {
                int a = o >> 6, c = o & 63;
                float s = 0.0f;
#pragma unroll
                for (int m = 0; m < MM; m++) {
                    int r = a * MM + m;
                    float f  = fmaf(buf[r * BUFSTR + c],        scS[c],      shS[c]);
                    float co = fmaf(buf[r * BUFSTR + 64 + c], scS[64 + c], shS[64 + c]);
                    s += sigm(f) * sftp(co);
                }
                g_summed[(n0 + a) * AFD + c] = s;
                ssum += s; ssq = fmaf(s, s, ssq);
            }
        }
    }

    // ---- deterministic per-block reduction (reuse A region) ----
    __syncthreads();
    if (PASS == 1) {
        float* sredS = (float*)base;               // [128][33]
        float* sredQ = (float*)(base + ALO_OFF);
        int widx = warp_m * 8 + (lane >> 2);
#pragma unroll
        for (int j = 0; j < 4; j++)
#pragma unroll
            for (int e = 0; e < 2; e++) {
                int c = N0 + j * 8 + (lane & 3) * 2 + e;
                sredS[c * 33 + widx] = sS[j * 2 + e];
                sredQ[c * 33 + widx] = sQ[j * 2 + e];
            }
        __syncthreads();
        if (tid < 256) {
            int stat = tid >> 7, c = tid & 127;
            const float* p = stat ? sredQ : sredS;
            float v = 0.0f;
#pragma unroll
            for (int w = 0; w < 32; w++) v += p[c * 33 + w];
            g_part1[blockIdx.x * 2 * CD + tid] = v;
        }
    } else {
        float* sred = (float*)base;
        sred[tid * 2] = ssum; sred[tid * 2 + 1] = ssq;
        __syncthreads();
        if (tid < 128) {
            int st = tid >> 6, c = tid & 63;
            float v = 0.0f;
#pragma unroll
            for (int g = 0; g < 8; g++) v += sred[(g * 64 + c) * 2 + st];
            g_part2[blockIdx.x * 2 * AFD + tid] = v;
        }
    }
}

// ---------------- BN finalize -------------------------------------------------
__global__ void fin1_k(const float* __restrict__ g, const float* __restrict__ b) {
    int c = threadIdx.x;
    float s = 0, q = 0;
    for (int bl = 0; bl < NBLK; bl++) {
        s += g_part1[bl * 2 * CD + c];
        q += g_part1[bl * 2 * CD + CD + c];
    }
    const float inv = 1.0f / ((float)NA * (float)MM);
    float mu = s * inv;
    float var = q * inv - mu * mu;
    float sc = g[c] * rsqrtf(var + EPSV);
    g_sc1[c] = sc;
    g_sh1[c] = b[c] - mu * sc;
}
__global__ void fin2_k(const float* __restrict__ g, const float* __restrict__ b) {
    int c = threadIdx.x;
    float s = 0, q = 0;
    for (int bl = 0; bl < NBLK; bl++) {
        s += g_part2[bl * 2 * AFD + c];
        q += g_part2[bl * 2 * AFD + AFD + c];
    }
    const float inv = 1.0f / (float)NA;
    float mu = s * inv;
    float var = q * inv - mu * mu;
    float sc = g[c] * rsqrtf(var + EPSV);
    g_sc2[c] = sc;
    g_sh2[c] = b[c] - mu * sc;
}

// ---------------- residual + bn2 + softplus ----------------------------------
__global__ void update_k(const float* __restrict__ fin, float* __restrict__ fout) {
    int i = blockIdx.x * blockDim.x + threadIdx.x;
    if (i < NA * AFD) {
        int c = i & 63;
        float v = fin[i] + fmaf(g_summed[i], g_sc2[c], g_sh2[c]);
        fout[i] = sftp(v);
    }
}

// ---------------- head -------------------------------------------------------
__global__ void head_k(const float* __restrict__ afea, const int* __restrict__ cai,
                       const float* __restrict__ Wfc, const float* __restrict__ bfc,
                       const float* __restrict__ Wout, const float* __restrict__ bout,
                       float* __restrict__ out) {
    __shared__ float scry[AFD];
    __shared__ float shid[HF];
    __shared__ float part[2][AFD];
    int b = blockIdx.x, t = threadIdx.x;
    int c = t & 63, h = t >> 6;

    const int* idx = cai + b * APC;
    float acc = 0;
    for (int a = h * (APC / 2); a < (h + 1) * (APC / 2); a++)
        acc += afea[idx[a] * AFD + c];
    part[h][c] = acc;
    __syncthreads();

    if (t < AFD) scry[t] = sftp((part[0][t] + part[1][t]) * (1.0f / (float)APC));
    __syncthreads();

    float a2 = bfc[t];
    for (int k = 0; k < AFD; k++) a2 = fmaf(scry[k], Wfc[k * HF + t], a2);
    shid[t] = sftp(a2);
    __syncthreads();

    if (t < HID) {
        float a3 = bout[t];
        for (int k = 0; k < HF; k++) a3 = fmaf(shid[k], Wout[k * HID + t], a3);
        out[b * HID + t] = a3;
    }
}

// ---------------- launch -----------------------------------------------------
extern "C" void kernel_launch(void* const* d_in, const int* in_sizes, int n_in,
                              void* d_out, int out_size) {
    const int*   atom_num = (const int*)d_in[0];
    const float* nbr_fea  = (const float*)d_in[1];
    const int*   nidx     = (const int*)d_in[2];
    const int*   cai      = (const int*)d_in[3];
    const float* emb      = (const float*)d_in[4];
    const float* W_full   = (const float*)d_in[5];
    const float* b_full   = (const float*)d_in[6];
    const float* bn1g     = (const float*)d_in[7];
    const float* bn1b     = (const float*)d_in[8];
    const float* bn2g     = (const float*)d_in[9];
    const float* bn2b     = (const float*)d_in[10];
    const float* Wfc      = (const float*)d_in[11];
    const float* bfc      = (const float*)d_in[12];
    const float* Wout     = (const float*)d_in[13];
    const float* bout     = (const float*)d_in[14];
    float* out = (float*)d_out;

    cudaFuncSetAttribute(conv4<1>, cudaFuncAttributeMaxDynamicSharedMemorySize, SMEM_DYN);
    cudaFuncSetAttribute(conv4<2>, cudaFuncAttributeMaxDynamicSharedMemorySize, SMEM_DYN);

    void *p0, *p1;
    cudaGetSymbolAddress(&p0, g_fea0);
    cudaGetSymbolAddress(&p1, g_fea1);
    float* fin  = (float*)p0;
    float* fout = (float*)p1;

    embed_k<<<(NA * AFD + 255) / 256, 256>>>(atom_num, emb);

    for (int i = 0; i < NCONV; i++) {
        const float* Wlp = W_full + (size_t)i * KD * CD;
        const float* blp = b_full + (size_t)i * CD;
        conv4<1><<<NBLK, 512, SMEM_DYN>>>(fin, nbr_fea, nidx, Wlp, blp);
        fin1_k<<<1, CD>>>(bn1g + (size_t)i * CD, bn1b + (size_t)i * CD);
        conv4<2><<<NBLK, 512, SMEM_DYN>>>(fin, nbr_fea, nidx, Wlp, blp);
        fin2_k<<<1, AFD>>>(bn2g + (size_t)i * AFD, bn2b + (size_t)i * AFD);
        update_k<<<(NA * AFD + 255) / 256, 256>>>(fin, fout);
        float* tmp = fin; fin = fout; fout = tmp;
    }

    head_k<<<NCRY, 128>>>(fin, cai, Wfc, bfc, Wout, bout, out);
}

// round 10
// speedup vs baseline: 8.3836x; 2.2289x over previous
#include <cuda_runtime.h>
#include <cuda_bf16.h>
#include <cstdint>

#define NA   100000
#define MM   12
#define AFD  64
#define NFD  41
#define KD   169
#define CD   128
#define NCONV 3
#define NCRY 100
#define APC  1000
#define HF   128
#define HID  64
#define EPSV 1e-5f

#define NBLK   148
#define TATOMS 5
#define NTILES (NA / TATOMS)   // 20000
#define TROWS  60
#define KSTEPS 11              // K = 176 (169 + pad)
#define ASTRE  184
#define ASTRB  368
#define NFP    48              // padded bond feature count (41 + 7 zeros)

#define G2BLK  1184            // pass2 streaming grid

// ---- SMEM byte offsets (from 1024-aligned base) ----
#define WHI_OFF   0u
#define WLO_OFF   47104u
#define A_OFF     94208u       // 2 stages x (hi 23552 | lo 23552)
#define STG_B     47104u
#define SREDS_OFF 188416u      // 128*17*4
#define SREDQ_OFF 197120u
#define BIAS_OFF  205824u
#define SIDX_OFF  206336u      // 2 x 64 i32
#define SMEM_USED 206848u
#define SMEM_DYN  (SMEM_USED + 1024u)

typedef unsigned long long ull;

// ---------------- scratch (device globals) ----------------------------------
__device__ float g_fea0[NA * AFD];
__device__ float g_fea1[NA * AFD];
__device__ float g_summed[NA * AFD];
__device__ float g_gated[NA * MM * CD];          // 614 MB fp32 scratch
__device__ __nv_bfloat16 g_AH[NA * AFD], g_AL[NA * AFD];
__device__ __nv_bfloat16 g_NH[NA * MM * NFP], g_NL[NA * MM * NFP];
__device__ float g_part1[NBLK * 2 * CD];
__device__ float g_part2[G2BLK * 2 * AFD];
__device__ float g_sc1[CD], g_sh1[CD];
__device__ float g_sc2[AFD], g_sh2[AFD];

// ---------------- helpers ----------------------------------------------------
__device__ __forceinline__ uint32_t smem_u32(const void* p) {
    uint32_t a;
    asm("{ .reg .u64 t; cvta.to.shared.u64 t, %1; cvt.u32.u64 %0, t; }"
        : "=r"(a) : "l"(p));
    return a;
}

#define LDSM4(r, addr) \
    asm volatile("ldmatrix.sync.aligned.m8n8.x4.shared.b16 {%0,%1,%2,%3},[%4];" \
        : "=r"((r)[0]), "=r"((r)[1]), "=r"((r)[2]), "=r"((r)[3]) : "r"(addr))

#define MMA16(c, a, b) \
    asm volatile("mma.sync.aligned.m16n8k16.row.col.f32.bf16.bf16.f32 " \
        "{%0,%1,%2,%3},{%4,%5,%6,%7},{%8,%9},{%0,%1,%2,%3};" \
        : "+f"((c)[0]), "+f"((c)[1]), "+f"((c)[2]), "+f"((c)[3]) \
        : "r"((a)[0]), "r"((a)[1]), "r"((a)[2]), "r"((a)[3]), \
          "r"((b)[0]), "r"((b)[1]))

#define CPA16(dst, src) \
    asm volatile("cp.async.cg.shared.global [%0],[%1],16;" \
        :: "r"(dst), "l"(src) : "memory")
#define CPA_COMMIT() asm volatile("cp.async.commit_group;" ::: "memory")
#define CPA_WAIT1()  asm volatile("cp.async.wait_group 1;" ::: "memory")

__device__ __forceinline__ void splitbf(float v, __nv_bfloat16& h, __nv_bfloat16& l) {
    h = __float2bfloat16(v);
    l = __float2bfloat16(v - __bfloat162float(h));
}

__device__ __forceinline__ float sigm(float x) {
    return __fdividef(1.0f, 1.0f + __expf(-x));
}
__device__ __forceinline__ float sftp(float x) {
    return fmaxf(x, 0.0f) + __logf(1.0f + __expf(-fabsf(x)));
}

// ---------------- embedding + bond preconversion -----------------------------
__global__ void embed2_k(const int* __restrict__ an, const float* __restrict__ emb) {
    int i = blockIdx.x * blockDim.x + threadIdx.x;
    if (i < NA * AFD) {
        int n = i >> 6, c = i & 63;
        float v = emb[an[n] * AFD + c];
        g_fea0[i] = v;
        splitbf(v, g_AH[i], g_AL[i]);
    }
}

__global__ void nbrcvt_k(const float* __restrict__ nbrf) {
    int i = blockIdx.x * blockDim.x + threadIdx.x;
    if (i < NA * MM * NFP) {
        int r = i / NFP, k = i - r * NFP;
        float v = (k < NFD) ? nbrf[r * NFD + k] : 0.0f;
        splitbf(v, g_NH[i], g_NL[i]);
    }
}

// ---------------- conv GEMM pass: gated -> g_gated + BN1 stats ---------------
// Tile: 64 rows (5 atoms x 12 nbrs + 4 pad) x 128 ch, K=176.
// 16 warps: warp_m = wid&1 (32 rows), warp_n = wid>>1 (16 cols).
// D = Ah*Wh + Ah*Wl + Al*Wh. cp.async double-buffered A staging.
__global__ void __launch_bounds__(512, 1) convg(
    const int*   __restrict__ nidx,
    const float* __restrict__ Wl,
    const float* __restrict__ bl)
{
    extern __shared__ char smraw[];
    char* base = (char*)((((uintptr_t)smraw) + 1023) & ~(uintptr_t)1023);
    const uint32_t bu = smem_u32(base);

    const int tid = threadIdx.x, wid = tid >> 5, lane = tid & 31;
    const int warp_m = wid & 1, warp_n = wid >> 1;
    const int R0 = warp_m * 32, N0 = warp_n * 16;

    float* biasS = (float*)(base + BIAS_OFF);
    int*   sIdx  = (int*)(base + SIDX_OFF);

    // zero all used SMEM (pad rows/cols of A and W stay zero forever)
    for (int i = tid; i < (int)(SMEM_USED / 4); i += 512) ((uint32_t*)base)[i] = 0;
    __syncthreads();

    // stage W^T hi/lo (rows = channels)
    for (int i = tid; i < KD * CD; i += 512) {
        int k = i >> 7, c = i & 127;
        __nv_bfloat16 h, l;
        splitbf(Wl[i], h, l);
        *(__nv_bfloat16*)(base + WHI_OFF + (c * ASTRE + k) * 2) = h;
        *(__nv_bfloat16*)(base + WLO_OFF + (c * ASTRE + k) * 2) = l;
    }
    if (tid < 128) biasS[tid] = bl[tid];

    // prologue: sIdx + stage tile0 into buffer 0
    int tile = blockIdx.x;
    if (tid < TROWS) sIdx[tid] = nidx[tile * TROWS + tid];
    __syncthreads();

    // staging helper (as macro-ish lambda)
    auto STAGE = [&](int t, int sbuf) {
        const int a0 = t * TATOMS;
        const int rbase = t * TROWS;
        const int* sx = sIdx + sbuf * 64;
        const uint32_t dH = bu + A_OFF + (uint32_t)sbuf * STG_B;
        const uint32_t dL = dH + 23552u;
        for (int i = tid; i < TROWS * 22; i += 512) {
            int r = i / 22, c = i - r * 22;
            uint32_t doff = (uint32_t)(r * ASTRB + c * 16);
            const char *sh, *sl;
            if (c < 8) {
                int off = (a0 + r / MM) * 128 + c * 16;
                sh = (const char*)g_AH + off; sl = (const char*)g_AL + off;
            } else if (c < 16) {
                int off = sx[r] * 128 + (c - 8) * 16;
                sh = (const char*)g_AH + off; sl = (const char*)g_AL + off;
            } else {
                int off = (rbase + r) * 96 + (c - 16) * 16;
                sh = (const char*)g_NH + off; sl = (const char*)g_NL + off;
            }
            CPA16(dH + doff, sh);
            CPA16(dL + doff, sl);
        }
    };

    STAGE(tile, 0);
    CPA_COMMIT();

    // per-thread bias (4 channels)
    float bch[4];
#pragma unroll
    for (int j = 0; j < 2; j++) {
        bch[j * 2 + 0] = biasS[N0 + j * 8 + (lane & 3) * 2];
        bch[j * 2 + 1] = biasS[N0 + j * 8 + (lane & 3) * 2 + 1];
    }

    // B operand addresses (static across tiles)
    const uint32_t boffb = (uint32_t)(((N0 + (lane & 7) + (lane >> 4) * 8) * ASTRE
                                      + ((lane >> 3) & 1) * 8) * 2);
    const uint32_t bHa = bu + WHI_OFF + boffb;
    const uint32_t bLa = bu + WLO_OFF + boffb;
    const uint32_t aoffb = (uint32_t)(((R0 + (lane & 15)) * ASTRE + (lane >> 4) * 8) * 2);

    float sS[4] = {0, 0, 0, 0}, sQ[4] = {0, 0, 0, 0};

    for (int it = 0; tile < NTILES; it++, tile += NBLK) {
        const int nxt = tile + NBLK;
        const int sb = it & 1;

        if (nxt < NTILES && tid < TROWS)
            sIdx[(sb ^ 1) * 64 + tid] = nidx[nxt * TROWS + tid];
        __syncthreads();                  // sIdx visible; prev GEMM done with buf sb^1
        if (nxt < NTILES) STAGE(nxt, sb ^ 1);
        CPA_COMMIT();
        CPA_WAIT1();                      // current tile's copies complete
        __syncthreads();

        // ---- GEMM on buffer sb ----
        const uint32_t AH = bu + A_OFF + (uint32_t)sb * STG_B;
        const uint32_t AL = AH + 23552u;
        const uint32_t aH0 = AH + aoffb, aH1 = aH0 + 16 * ASTRB;
        const uint32_t aL0 = AL + aoffb, aL1 = aL0 + 16 * ASTRB;

        float C[2][2][4];
#pragma unroll
        for (int mi = 0; mi < 2; mi++)
#pragma unroll
            for (int j = 0; j < 2; j++)
#pragma unroll
                for (int p = 0; p < 4; p++) C[mi][j][p] = 0.0f;

#pragma unroll
        for (int ks = 0; ks < KSTEPS; ks++) {
            const uint32_t ko = (uint32_t)ks * 32u;
            uint32_t ah0[4], ah1[4], al0[4], al1[4], wh[4], wl[4];
            LDSM4(ah0, aH0 + ko); LDSM4(ah1, aH1 + ko);
            LDSM4(wh, bHa + ko);
            MMA16(C[0][0], ah0, wh + 0); MMA16(C[0][1], ah0, wh + 2);
            MMA16(C[1][0], ah1, wh + 0); MMA16(C[1][1], ah1, wh + 2);
            LDSM4(wl, bLa + ko);
            MMA16(C[0][0], ah0, wl + 0); MMA16(C[0][1], ah0, wl + 2);
            MMA16(C[1][0], ah1, wl + 0); MMA16(C[1][1], ah1, wl + 2);
            LDSM4(al0, aL0 + ko); LDSM4(al1, aL1 + ko);
            MMA16(C[0][0], al0, wh + 0); MMA16(C[0][1], al0, wh + 2);
            MMA16(C[1][0], al1, wh + 0); MMA16(C[1][1], al1, wh + 2);
        }

        // ---- epilogue: +bias, store gated fp32, accumulate stats ----
        const int growb = tile * TROWS;
#pragma unroll
        for (int mi = 0; mi < 2; mi++) {
            const int r0 = R0 + mi * 16 + (lane >> 2);
            const int r1 = r0 + 8;
#pragma unroll
            for (int j = 0; j < 2; j++) {
                const int col = N0 + j * 8 + (lane & 3) * 2;
                float g0 = C[mi][j][0] + bch[j * 2];
                float g1 = C[mi][j][1] + bch[j * 2 + 1];
                float g2 = C[mi][j][2] + bch[j * 2];
                float g3 = C[mi][j][3] + bch[j * 2 + 1];
                // r0 always < 60
                *(float2*)&g_gated[(growb + r0) * CD + col] = make_float2(g0, g1);
                sS[j * 2] += g0; sS[j * 2 + 1] += g1;
                sQ[j * 2] = fmaf(g0, g0, sQ[j * 2]);
                sQ[j * 2 + 1] = fmaf(g1, g1, sQ[j * 2 + 1]);
                if (r1 < TROWS) {
                    *(float2*)&g_gated[(growb + r1) * CD + col] = make_float2(g2, g3);
                    sS[j * 2] += g2; sS[j * 2 + 1] += g3;
                    sQ[j * 2] = fmaf(g2, g2, sQ[j * 2]);
                    sQ[j * 2 + 1] = fmaf(g3, g3, sQ[j * 2 + 1]);
                }
            }
        }
    }

    // ---- deterministic per-block stat reduction ----
    __syncthreads();
    {
        float* sredS = (float*)(base + SREDS_OFF);   // [128][17]
        float* sredQ = (float*)(base + SREDQ_OFF);
        const int idx = warp_m * 8 + (lane >> 2);
#pragma unroll
        for (int j = 0; j < 2; j++)
#pragma unroll
            for (int e = 0; e < 2; e++) {
                int c = N0 + j * 8 + (lane & 3) * 2 + e;
                sredS[c * 17 + idx] = sS[j * 2 + e];
                sredQ[c * 17 + idx] = sQ[j * 2 + e];
            }
        __syncthreads();
        if (tid < 256) {
            int stat = tid >> 7, c = tid & 127;
            const float* p = stat ? sredQ : sredS;
            float v = 0.0f;
#pragma unroll
            for (int w = 0; w < 16; w++) v += p[c * 17 + w];
            g_part1[blockIdx.x * 2 * CD + tid] = v;
        }
    }
}

// ---------------- streaming pass2: bn1 -> act -> 12-sum + BN2 stats ----------
__global__ void __launch_bounds__(256) pass2s_k() {
    const int tid = threadIdx.x;
    const int o0 = blockIdx.x * 256 + tid;
    const int c = o0 & 63;   // invariant across grid stride (stride % 64 == 0)
    const float scF = g_sc1[c],      shF = g_sh1[c];
    const float scC = g_sc1[64 + c], shC = g_sh1[64 + c];

    float ssum = 0.0f, ssq = 0.0f;
    for (int o = o0; o < NA * AFD; o += G2BLK * 256) {
        const int n = o >> 6;
        const float* gp = g_gated + n * (MM * CD);
        float s = 0.0f;
#pragma unroll
        for (int m = 0; m < MM; m++) {
            float f  = fmaf(gp[m * CD + c],      scF, shF);
            float co = fmaf(gp[m * CD + 64 + c], scC, shC);
            s += sigm(f) * sftp(co);
        }
        g_summed[o] = s;
        ssum += s; ssq = fmaf(s, s, ssq);
    }

    __shared__ float sr[512];
    sr[tid] = ssum; sr[256 + tid] = ssq;
    __syncthreads();
    if (tid < 128) {
        int st = tid >> 6, cc = tid & 63;
        const float* b = sr + st * 256;
        float v = b[cc] + b[cc + 64] + b[cc + 128] + b[cc + 192];
        g_part2[blockIdx.x * 128 + tid] = v;
    }
}

// ---------------- BN finalize -------------------------------------------------
__global__ void fin1_k(const float* __restrict__ g, const float* __restrict__ b) {
    int c = threadIdx.x;   // 128
    float s = 0, q = 0;
    for (int bl = 0; bl < NBLK; bl++) {
        s += g_part1[bl * 2 * CD + c];
        q += g_part1[bl * 2 * CD + CD + c];
    }
    const float inv = 1.0f / ((float)NA * (float)MM);
    float mu = s * inv;
    float var = q * inv - mu * mu;
    float sc = g[c] * rsqrtf(var + EPSV);
    g_sc1[c] = sc;
    g_sh1[c] = b[c] - mu * sc;
}
__global__ void fin2_k(const float* __restrict__ g, const float* __restrict__ b) {
    int c = threadIdx.x;   // 64
    float s = 0, q = 0;
    for (int bl = 0; bl < G2BLK; bl++) {
        s += g_part2[bl * 128 + c];
        q += g_part2[bl * 128 + 64 + c];
    }
    const float inv = 1.0f / (float)NA;
    float mu = s * inv;
    float var = q * inv - mu * mu;
    float sc = g[c] * rsqrtf(var + EPSV);
    g_sc2[c] = sc;
    g_sh2[c] = b[c] - mu * sc;
}

// ---------------- residual + bn2 + softplus (+ bf16 hi/lo for next layer) ----
__global__ void update_k(const float* __restrict__ fin, float* __restrict__ fout) {
    int i = blockIdx.x * blockDim.x + threadIdx.x;
    if (i < NA * AFD) {
        int c = i & 63;
        float v = sftp(fin[i] + fmaf(g_summed[i], g_sc2[c], g_sh2[c]));
        fout[i] = v;
        splitbf(v, g_AH[i], g_AL[i]);
    }
}

// ---------------- head -------------------------------------------------------
__global__ void head_k(const float* __restrict__ afea, const int* __restrict__ cai,
                       const float* __restrict__ Wfc, const float* __restrict__ bfc,
                       const float* __restrict__ Wout, const float* __restrict__ bout,
                       float* __restrict__ out) {
    __shared__ float scry[AFD];
    __shared__ float shid[HF];
    __shared__ float part[2][AFD];
    int b = blockIdx.x, t = threadIdx.x;
    int c = t & 63, h = t >> 6;

    const int* idx = cai + b * APC;
    float acc = 0;
    for (int a = h * (APC / 2); a < (h + 1) * (APC / 2); a++)
        acc += afea[idx[a] * AFD + c];
    part[h][c] = acc;
    __syncthreads();

    if (t < AFD) scry[t] = sftp((part[0][t] + part[1][t]) * (1.0f / (float)APC));
    __syncthreads();

    float a2 = bfc[t];
    for (int k = 0; k < AFD; k++) a2 = fmaf(scry[k], Wfc[k * HF + t], a2);
    shid[t] = sftp(a2);
    __syncthreads();

    if (t < HID) {
        float a3 = bout[t];
        for (int k = 0; k < HF; k++) a3 = fmaf(shid[k], Wout[k * HID + t], a3);
        out[b * HID + t] = a3;
    }
}

// ---------------- launch -----------------------------------------------------
extern "C" void kernel_launch(void* const* d_in, const int* in_sizes, int n_in,
                              void* d_out, int out_size) {
    const int*   atom_num = (const int*)d_in[0];
    const float* nbr_fea  = (const float*)d_in[1];
    const int*   nidx     = (const int*)d_in[2];
    const int*   cai      = (const int*)d_in[3];
    const float* emb      = (const float*)d_in[4];
    const float* W_full   = (const float*)d_in[5];
    const float* b_full   = (const float*)d_in[6];
    const float* bn1g     = (const float*)d_in[7];
    const float* bn1b     = (const float*)d_in[8];
    const float* bn2g     = (const float*)d_in[9];
    const float* bn2b     = (const float*)d_in[10];
    const float* Wfc      = (const float*)d_in[11];
    const float* bfc      = (const float*)d_in[12];
    const float* Wout     = (const float*)d_in[13];
    const float* bout     = (const float*)d_in[14];
    float* out = (float*)d_out;

    cudaFuncSetAttribute(convg, cudaFuncAttributeMaxDynamicSharedMemorySize, SMEM_DYN);

    void *p0, *p1;
    cudaGetSymbolAddress(&p0, g_fea0);
    cudaGetSymbolAddress(&p1, g_fea1);
    float* fin  = (float*)p0;
    float* fout = (float*)p1;

    embed2_k<<<(NA * AFD + 255) / 256, 256>>>(atom_num, emb);
    nbrcvt_k<<<(NA * MM * NFP + 255) / 256, 256>>>(nbr_fea);

    for (int i = 0; i < NCONV; i++) {
        const float* Wlp = W_full + (size_t)i * KD * CD;
        const float* blp = b_full + (size_t)i * CD;
        convg<<<NBLK, 512, SMEM_DYN>>>(nidx, Wlp, blp);
        fin1_k<<<1, CD>>>(bn1g + (size_t)i * CD, bn1b + (size_t)i * CD);
        pass2s_k<<<G2BLK, 256>>>();
        fin2_k<<<1, AFD>>>(bn2g + (size_t)i * AFD, bn2b + (size_t)i * AFD);
        update_k<<<(NA * AFD + 255) / 256, 256>>>(fin, fout);
        float* tmp = fin; fin = fout; fout = tmp;
    }

    head_k<<<NCRY, 128>>>(fin, cai, Wfc, bfc, Wout, bout, out);
}

// round 12
// speedup vs baseline: 8.6096x; 1.0270x over previous
#include <cuda_runtime.h>
#include <cuda_bf16.h>
#include <cstdint>

#define NA   100000
#define MM   12
#define AFD  64
#define NFD  41
#define KD   169
#define CD   128
#define NCONV 3
#define NCRY 100
#define APC  1000
#define HF   128
#define HID  64
#define EPSV 1e-5f

#define NBLK   148
#define TATOMS 10
#define NTILES (NA / TATOMS)   // 10000
#define TROWS  120
#define KSTEPS 7               // K_rest = 112 (64 nbr + 48 bond-pad)
#define ASTRE  120             // elems per row (240 B = 15x16B, conflict-free)
#define ASTRB  240
#define NFP    48

#define G2BLK  1184

// ---- convg SMEM byte offsets (from 1024-aligned base) ----
#define WHI_OFF   0u           // 128 ch x 120 k x 2B = 30720
#define WLO_OFF   30720u
#define A_OFF     61440u       // 2 stages x 61440 (hi 30720 | lo 30720)
#define STG_B     61440u
#define SIDX_OFF  184320u      // 2 x 128 i32
#define SMEM_USED 185344u
#define SMEM_DYN  (SMEM_USED + 1024u)
// stat-reduction overlays (reuse W/A region after mainloop)
#define SREDS_OFF 0u
#define SREDQ_OFF 16896u       // 128*33*4

// ---- selfg SMEM ----
#define SGA_HI  0u             // 128 x 144B
#define SGA_LO  18432u
#define SGW_HI  36864u
#define SGW_LO  55296u
#define SGBIAS  73728u
#define SG_USED 74240u
#define SG_DYN  (SG_USED + 1024u)

typedef unsigned long long ull;

// ---------------- scratch (device globals) ----------------------------------
__device__ float g_fea0[NA * AFD];
__device__ float g_fea1[NA * AFD];
__device__ float g_summed[NA * AFD];
__device__ float g_gated[NA * MM * CD];          // 614 MB fp32
__device__ float g_self[NA * CD];                // 205 MB fp32
__device__ __nv_bfloat16 g_AH[NA * AFD], g_AL[NA * AFD];
__device__ __nv_bfloat16 g_NH[NA * MM * NFP], g_NL[NA * MM * NFP];
__device__ float g_part1[NBLK * 2 * CD];
__device__ float g_part2[G2BLK * 2 * AFD];
__device__ float g_sc1[CD], g_sh1[CD];
__device__ float g_sc2[AFD], g_sh2[AFD];

// ---------------- helpers ----------------------------------------------------
__device__ __forceinline__ uint32_t smem_u32(const void* p) {
    uint32_t a;
    asm("{ .reg .u64 t; cvta.to.shared.u64 t, %1; cvt.u32.u64 %0, t; }"
        : "=r"(a) : "l"(p));
    return a;
}

#define LDSM4(r, addr) \
    asm volatile("ldmatrix.sync.aligned.m8n8.x4.shared.b16 {%0,%1,%2,%3},[%4];" \
        : "=r"((r)[0]), "=r"((r)[1]), "=r"((r)[2]), "=r"((r)[3]) : "r"(addr))

#define MMA16(c, a, b) \
    asm volatile("mma.sync.aligned.m16n8k16.row.col.f32.bf16.bf16.f32 " \
        "{%0,%1,%2,%3},{%4,%5,%6,%7},{%8,%9},{%0,%1,%2,%3};" \
        : "+f"((c)[0]), "+f"((c)[1]), "+f"((c)[2]), "+f"((c)[3]) \
        : "r"((a)[0]), "r"((a)[1]), "r"((a)[2]), "r"((a)[3]), \
          "r"((b)[0]), "r"((b)[1]))

#define CPA16(dst, src) \
    asm volatile("cp.async.cg.shared.global [%0],[%1],16;" \
        :: "r"(dst), "l"(src) : "memory")
#define CPA_COMMIT() asm volatile("cp.async.commit_group;" ::: "memory")
#define CPA_WAIT1()  asm volatile("cp.async.wait_group 1;" ::: "memory")

__device__ __forceinline__ void splitbf(float v, __nv_bfloat16& h, __nv_bfloat16& l) {
    h = __float2bfloat16(v);
    l = __float2bfloat16(v - __bfloat162float(h));
}
__device__ __forceinline__ float sigm(float x) {
    return __fdividef(1.0f, 1.0f + __expf(-x));
}
__device__ __forceinline__ float sftp(float x) {
    return fmaxf(x, 0.0f) + __logf(1.0f + __expf(-fabsf(x)));
}

// ---------------- embedding + bond preconversion -----------------------------
__global__ void embed2_k(const int* __restrict__ an, const float* __restrict__ emb) {
    int i = blockIdx.x * blockDim.x + threadIdx.x;
    if (i < NA * AFD) {
        int n = i >> 6, c = i & 63;
        float v = emb[an[n] * AFD + c];
        g_fea0[i] = v;
        splitbf(v, g_AH[i], g_AL[i]);
    }
}
__global__ void nbrcvt_k(const float* __restrict__ nbrf) {
    int i = blockIdx.x * blockDim.x + threadIdx.x;
    if (i < NA * MM * NFP) {
        int r = i / NFP, k = i - r * NFP;
        float v = (k < NFD) ? nbrf[r * NFD + k] : 0.0f;
        splitbf(v, g_NH[i], g_NL[i]);
    }
}

// ---------------- selfg: S = atom_fea @ W[0:64] + bias -----------------------
// 128 rows x 128 ch per block, K=64 (4 ksteps). One-shot staging.
__global__ void __launch_bounds__(512, 1) selfg_k(
    const float* __restrict__ Wl, const float* __restrict__ bl)
{
    extern __shared__ char smraw[];
    char* base = (char*)((((uintptr_t)smraw) + 1023) & ~(uintptr_t)1023);
    const uint32_t bu = smem_u32(base);

    const int tid = threadIdx.x, wid = tid >> 5, lane = tid & 31;
    const int warp_m = wid & 3, warp_n = wid >> 2;
    const int R0 = warp_m * 32, N0 = warp_n * 32;
    const int n0 = blockIdx.x * 128;

    for (int i = tid; i < (int)(SG_USED / 4); i += 512) ((uint32_t*)base)[i] = 0;
    __syncthreads();

    // stage A (guarded), 16B chunks; 144B row stride
    for (int i = tid; i < 128 * 8; i += 512) {
        int r = i >> 3, c = i & 7;
        uint4 vh = make_uint4(0, 0, 0, 0), vl = make_uint4(0, 0, 0, 0);
        if (n0 + r < NA) {
            vh = *(const uint4*)((const char*)g_AH + (size_t)(n0 + r) * 128 + c * 16);
            vl = *(const uint4*)((const char*)g_AL + (size_t)(n0 + r) * 128 + c * 16);
        }
        *(uint4*)(base + SGA_HI + r * 144 + c * 16) = vh;
        *(uint4*)(base + SGA_LO + r * 144 + c * 16) = vl;
    }
    // stage W^T hi/lo (rows = channels, k = 0..63)
    for (int i = tid; i < 64 * 128; i += 512) {
        int k = i >> 7, c = i & 127;
        __nv_bfloat16 h, l;
        splitbf(Wl[k * CD + c], h, l);
        *(__nv_bfloat16*)(base + SGW_HI + c * 144 + k * 2) = h;
        *(__nv_bfloat16*)(base + SGW_LO + c * 144 + k * 2) = l;
    }
    if (tid < 128) ((float*)(base + SGBIAS))[tid] = bl[tid];
    __syncthreads();

    const uint32_t aoffb = (uint32_t)(((R0 + (lane & 15)) * 72 + (lane >> 4) * 8) * 2);
    const uint32_t aH0 = bu + SGA_HI + aoffb, aH1 = aH0 + 16 * 144;
    const uint32_t aL0 = bu + SGA_LO + aoffb, aL1 = aL0 + 16 * 144;
    const uint32_t boffb = (uint32_t)(((N0 + (lane & 7) + (lane >> 4) * 8) * 72
                                      + ((lane >> 3) & 1) * 8) * 2);
    const uint32_t bH0 = bu + SGW_HI + boffb, bH1 = bH0 + 16 * 144;
    const uint32_t bL0 = bu + SGW_LO + boffb, bL1 = bL0 + 16 * 144;

    float bch[8];
#pragma unroll
    for (int j = 0; j < 4; j++) {
        bch[j * 2]     = ((float*)(base + SGBIAS))[N0 + j * 8 + (lane & 3) * 2];
        bch[j * 2 + 1] = ((float*)(base + SGBIAS))[N0 + j * 8 + (lane & 3) * 2 + 1];
    }

    float C[2][4][4];
#pragma unroll
    for (int mi = 0; mi < 2; mi++)
#pragma unroll
        for (int j = 0; j < 4; j++)
#pragma unroll
            for (int p = 0; p < 4; p++) C[mi][j][p] = 0.0f;

#pragma unroll
    for (int ks = 0; ks < 4; ks++) {
        const uint32_t ko = (uint32_t)ks * 32u;
        uint32_t ah0[4], ah1[4], al0[4], al1[4], whA[4], whB[4], wlA[4], wlB[4];
        LDSM4(ah0, aH0 + ko); LDSM4(ah1, aH1 + ko);
        LDSM4(whA, bH0 + ko); LDSM4(whB, bH1 + ko);
        MMA16(C[0][0], ah0, whA + 0); MMA16(C[0][1], ah0, whA + 2);
        MMA16(C[0][2], ah0, whB + 0); MMA16(C[0][3], ah0, whB + 2);
        MMA16(C[1][0], ah1, whA + 0); MMA16(C[1][1], ah1, whA + 2);
        MMA16(C[1][2], ah1, whB + 0); MMA16(C[1][3], ah1, whB + 2);
        LDSM4(wlA, bL0 + ko); LDSM4(wlB, bL1 + ko);
        MMA16(C[0][0], ah0, wlA + 0); MMA16(C[0][1], ah0, wlA + 2);
        MMA16(C[0][2], ah0, wlB + 0); MMA16(C[0][3], ah0, wlB + 2);
        MMA16(C[1][0], ah1, wlA + 0); MMA16(C[1][1], ah1, wlA + 2);
        MMA16(C[1][2], ah1, wlB + 0); MMA16(C[1][3], ah1, wlB + 2);
        LDSM4(al0, aL0 + ko); LDSM4(al1, aL1 + ko);
        MMA16(C[0][0], al0, whA + 0); MMA16(C[0][1], al0, whA + 2);
        MMA16(C[0][2], al0, whB + 0); MMA16(C[0][3], al0, whB + 2);
        MMA16(C[1][0], al1, whA + 0); MMA16(C[1][1], al1, whA + 2);
        MMA16(C[1][2], al1, whB + 0); MMA16(C[1][3], al1, whB + 2);
    }

#pragma unroll
    for (int mi = 0; mi < 2; mi++) {
        int r0 = R0 + mi * 16 + (lane >> 2);
        int r1 = r0 + 8;
#pragma unroll
        for (int j = 0; j < 4; j++) {
            int col = N0 + j * 8 + (lane & 3) * 2;
            if (n0 + r0 < NA)
                *(float2*)&g_self[(size_t)(n0 + r0) * CD + col] =
                    make_float2(C[mi][j][0] + bch[j * 2], C[mi][j][1] + bch[j * 2 + 1]);
            if (n0 + r1 < NA)
                *(float2*)&g_self[(size_t)(n0 + r1) * CD + col] =
                    make_float2(C[mi][j][2] + bch[j * 2], C[mi][j][3] + bch[j * 2 + 1]);
        }
    }
}

// ---------------- convg: rest-GEMM (K=112) + self add -> gated + BN1 stats ---
__global__ void __launch_bounds__(512, 1) convg(const int* __restrict__ nidx,
                                                const float* __restrict__ Wl)
{
    extern __shared__ char smraw[];
    char* base = (char*)((((uintptr_t)smraw) + 1023) & ~(uintptr_t)1023);
    const uint32_t bu = smem_u32(base);

    const int tid = threadIdx.x, wid = tid >> 5, lane = tid & 31;
    const int warp_m = wid & 3, warp_n = wid >> 2;
    const int R0 = warp_m * 32, N0 = warp_n * 32;
    int* sIdx = (int*)(base + SIDX_OFF);

    for (int i = tid; i < (int)(SMEM_USED / 4); i += 512) ((uint32_t*)base)[i] = 0;
    __syncthreads();

    // W^T hi/lo for k_global 64..168 (local 0..104; 105..111 stay zero)
    for (int i = tid; i < 105 * 128; i += 512) {
        int k = i >> 7, c = i & 127;
        __nv_bfloat16 h, l;
        splitbf(Wl[(64 + k) * CD + c], h, l);
        *(__nv_bfloat16*)(base + WHI_OFF + c * ASTRB + k * 2) = h;
        *(__nv_bfloat16*)(base + WLO_OFF + c * ASTRB + k * 2) = l;
    }

    int tile = blockIdx.x;
    if (tid < TROWS) sIdx[tid] = nidx[tile * TROWS + tid];
    __syncthreads();

    auto STAGE = [&](int t, int sbuf) {
        const int rbase = t * TROWS;
        const int* sx = sIdx + sbuf * 128;
        const uint32_t dH = bu + A_OFF + (uint32_t)sbuf * STG_B;
        const uint32_t dL = dH + 30720u;
        for (int i = tid; i < TROWS * 14; i += 512) {
            int r = i / 14, c = i - r * 14;
            const char *sh, *sl;
            uint32_t doff;
            if (c < 8) {                 // neighbor features -> k 0..63
                size_t off = (size_t)sx[r] * 128 + c * 16;
                sh = (const char*)g_AH + off; sl = (const char*)g_AL + off;
                doff = (uint32_t)(r * ASTRB + c * 16);
            } else {                     // bond features -> k 64..111
                size_t off = (size_t)(rbase + r) * 96 + (c - 8) * 16;
                sh = (const char*)g_NH + off; sl = (const char*)g_NL + off;
                doff = (uint32_t)(r * ASTRB + 128 + (c - 8) * 16);
            }
            CPA16(dH + doff, sh);
            CPA16(dL + doff, sl);
        }
    };

    STAGE(tile, 0);
    CPA_COMMIT();

    const uint32_t aoffb = (uint32_t)(((R0 + (lane & 15)) * ASTRE + (lane >> 4) * 8) * 2);
    const uint32_t boffb = (uint32_t)(((N0 + (lane & 7) + (lane >> 4) * 8) * ASTRE
                                      + ((lane >> 3) & 1) * 8) * 2);
    const uint32_t bH0 = bu + WHI_OFF + boffb, bH1 = bH0 + 16 * ASTRB;
    const uint32_t bL0 = bu + WLO_OFF + boffb, bL1 = bL0 + 16 * ASTRB;

    float sS[8], sQ[8];
#pragma unroll
    for (int j = 0; j < 8; j++) { sS[j] = 0.0f; sQ[j] = 0.0f; }

    for (int it = 0; tile < NTILES; it++, tile += NBLK) {
        const int nxt = tile + NBLK;
        const int sb = it & 1;

        if (nxt < NTILES && tid < TROWS)
            sIdx[(sb ^ 1) * 128 + tid] = nidx[nxt * TROWS + tid];
        __syncthreads();               // prev GEMM done with buf sb^1; sIdx visible
        if (nxt < NTILES) STAGE(nxt, sb ^ 1);
        CPA_COMMIT();
        CPA_WAIT1();
        __syncthreads();

        const uint32_t AH = bu + A_OFF + (uint32_t)sb * STG_B;
        const uint32_t AL = AH + 30720u;
        const uint32_t aH0 = AH + aoffb, aH1 = aH0 + 16 * ASTRB;
        const uint32_t aL0 = AL + aoffb, aL1 = aL0 + 16 * ASTRB;

        float C[2][4][4];
#pragma unroll
        for (int mi = 0; mi < 2; mi++)
#pragma unroll
            for (int j = 0; j < 4; j++)
#pragma unroll
                for (int p = 0; p < 4; p++) C[mi][j][p] = 0.0f;

#pragma unroll
        for (int ks = 0; ks < KSTEPS; ks++) {
            const uint32_t ko = (uint32_t)ks * 32u;
            uint32_t ah0[4], ah1[4], al0[4], al1[4], whA[4], whB[4], wlA[4], wlB[4];
            LDSM4(ah0, aH0 + ko); LDSM4(ah1, aH1 + ko);
            LDSM4(whA, bH0 + ko); LDSM4(whB, bH1 + ko);
            MMA16(C[0][0], ah0, whA + 0); MMA16(C[0][1], ah0, whA + 2);
            MMA16(C[0][2], ah0, whB + 0); MMA16(C[0][3], ah0, whB + 2);
            MMA16(C[1][0], ah1, whA + 0); MMA16(C[1][1], ah1, whA + 2);
            MMA16(C[1][2], ah1, whB + 0); MMA16(C[1][3], ah1, whB + 2);
            LDSM4(wlA, bL0 + ko); LDSM4(wlB, bL1 + ko);
            MMA16(C[0][0], ah0, wlA + 0); MMA16(C[0][1], ah0, wlA + 2);
            MMA16(C[0][2], ah0, wlB + 0); MMA16(C[0][3], ah0, wlB + 2);
            MMA16(C[1][0], ah1, wlA + 0); MMA16(C[1][1], ah1, wlA + 2);
            MMA16(C[1][2], ah1, wlB + 0); MMA16(C[1][3], ah1, wlB + 2);
            LDSM4(al0, aL0 + ko); LDSM4(al1, aL1 + ko);
            MMA16(C[0][0], al0, whA + 0); MMA16(C[0][1], al0, whA + 2);
            MMA16(C[0][2], al0, whB + 0); MMA16(C[0][3], al0, whB + 2);
            MMA16(C[1][0], al1, whA + 0); MMA16(C[1][1], al1, whA + 2);
            MMA16(C[1][2], al1, whB + 0); MMA16(C[1][3], al1, whB + 2);
        }

        // ---- epilogue: + self[atom], store gated fp32, accumulate stats ----
        const int growb = tile * TROWS;
        const int atomb = tile * TATOMS;
#pragma unroll
        for (int mi = 0; mi < 2; mi++) {
            const int r0 = R0 + mi * 16 + (lane >> 2);
            const int r1 = r0 + 8;
            const bool v1 = (r1 < TROWS);     // false only warp_m==3, mi==1
            const int a0 = atomb + r0 / MM;
            const int a1 = atomb + r1 / MM;
#pragma unroll
            for (int j = 0; j < 4; j++) {
                const int col = N0 + j * 8 + (lane & 3) * 2;
                float2 s0 = *(const float2*)&g_self[(size_t)a0 * CD + col];
                float g0 = C[mi][j][0] + s0.x;
                float g1 = C[mi][j][1] + s0.y;
                *(float2*)&g_gated[(size_t)(growb + r0) * CD + col] = make_float2(g0, g1);
                sS[j * 2] += g0; sS[j * 2 + 1] += g1;
                sQ[j * 2] = fmaf(g0, g0, sQ[j * 2]);
                sQ[j * 2 + 1] = fmaf(g1, g1, sQ[j * 2 + 1]);
                if (v1) {
                    float2 s1 = *(const float2*)&g_self[(size_t)a1 * CD + col];
                    float g2 = C[mi][j][2] + s1.x;
                    float g3 = C[mi][j][3] + s1.y;
                    *(float2*)&g_gated[(size_t)(growb + r1) * CD + col] = make_float2(g2, g3);
                    sS[j * 2] += g2; sS[j * 2 + 1] += g3;
                    sQ[j * 2] = fmaf(g2, g2, sQ[j * 2]);
                    sQ[j * 2 + 1] = fmaf(g3, g3, sQ[j * 2 + 1]);
                }
            }
        }
    }

    // ---- deterministic per-block stat reduction (overlay W/A region) ----
    __syncthreads();
    {
        float* sredS = (float*)(base + SREDS_OFF);   // [128][33]
        float* sredQ = (float*)(base + SREDQ_OFF);
        const int idx = warp_m * 8 + (lane >> 2);
#pragma unroll
        for (int j = 0; j < 4; j++)
#pragma unroll
            for (int e = 0; e < 2; e++) {
                int c = N0 + j * 8 + (lane & 3) * 2 + e;
                sredS[c * 33 + idx] = sS[j * 2 + e];
                sredQ[c * 33 + idx] = sQ[j * 2 + e];
            }
        __syncthreads();
        if (tid < 256) {
            int stat = tid >> 7, c = tid & 127;
            const float* p = stat ? sredQ : sredS;
            float v = 0.0f;
#pragma unroll
            for (int w = 0; w < 32; w++) v += p[c * 33 + w];
            g_part1[blockIdx.x * 2 * CD + tid] = v;
        }
    }
}

// ---------------- streaming pass2 --------------------------------------------
__global__ void __launch_bounds__(256) pass2s_k() {
    const int tid = threadIdx.x;
    const int o0 = blockIdx.x * 256 + tid;
    const int c = o0 & 63;
    const float scF = g_sc1[c],      shF = g_sh1[c];
    const float scC = g_sc1[64 + c], shC = g_sh1[64 + c];

    float ssum = 0.0f, ssq = 0.0f;
    for (int o = o0; o < NA * AFD; o += G2BLK * 256) {
        const int n = o >> 6;
        const float* gp = g_gated + (size_t)n * (MM * CD);
        float s = 0.0f;
#pragma unroll
        for (int m = 0; m < MM; m++) {
            float f  = fmaf(gp[m * CD + c],      scF, shF);
            float co = fmaf(gp[m * CD + 64 + c], scC, shC);
            s += sigm(f) * sftp(co);
        }
        g_summed[o] = s;
        ssum += s; ssq = fmaf(s, s, ssq);
    }

    __shared__ float sr[512];
    sr[tid] = ssum; sr[256 + tid] = ssq;
    __syncthreads();
    if (tid < 128) {
        int st = tid >> 6, cc = tid & 63;
        const float* b = sr + st * 256;
        g_part2[blockIdx.x * 128 + tid] = b[cc] + b[cc + 64] + b[cc + 128] + b[cc + 192];
    }
}

// ---------------- BN finalize (parallelized) ---------------------------------
__global__ void __launch_bounds__(512) fin1_k(const float* __restrict__ g,
                                              const float* __restrict__ b) {
    __shared__ float sm[2][512];
    int tid = threadIdx.x, c = tid & 127, grp = tid >> 7;   // 4 slices
    float s = 0, q = 0;
    for (int bl = grp; bl < NBLK; bl += 4) {
        s += g_part1[bl * 2 * CD + c];
        q += g_part1[bl * 2 * CD + CD + c];
    }
    sm[0][tid] = s; sm[1][tid] = q;
    __syncthreads();
    if (tid < 128) {
        float S = sm[0][tid] + sm[0][128 + tid] + sm[0][256 + tid] + sm[0][384 + tid];
        float Q = sm[1][tid] + sm[1][128 + tid] + sm[1][256 + tid] + sm[1][384 + tid];
        const float inv = 1.0f / ((float)NA * (float)MM);
        float mu = S * inv;
        float var = Q * inv - mu * mu;
        float sc = g[tid] * rsqrtf(var + EPSV);
        g_sc1[tid] = sc;
        g_sh1[tid] = b[tid] - mu * sc;
    }
}
__global__ void __launch_bounds__(512) fin2_k(const float* __restrict__ g,
                                              const float* __restrict__ b) {
    __shared__ float sm[2][512];
    int tid = threadIdx.x, c = tid & 63, grp = tid >> 6;    // 8 slices
    float s = 0, q = 0;
    for (int bl = grp; bl < G2BLK; bl += 8) {
        s += g_part2[bl * 128 + c];
        q += g_part2[bl * 128 + 64 + c];
    }
    sm[0][tid] = s; sm[1][tid] = q;
    __syncthreads();
    if (tid < 64) {
        float S = 0, Q = 0;
#pragma unroll
        for (int w = 0; w < 8; w++) { S += sm[0][w * 64 + tid]; Q += sm[1][w * 64 + tid]; }
        const float inv = 1.0f / (float)NA;
        float mu = S * inv;
        float var = Q * inv - mu * mu;
        float sc = g[tid] * rsqrtf(var + EPSV);
        g_sc2[tid] = sc;
        g_sh2[tid] = b[tid] - mu * sc;
    }
}

// ---------------- residual + bn2 + softplus (+ bf16 hi/lo) -------------------
__global__ void update_k(const float* __restrict__ fin, float* __restrict__ fout) {
    int i = blockIdx.x * blockDim.x + threadIdx.x;
    if (i < NA * AFD) {
        int c = i & 63;
        float v = sftp(fin[i] + fmaf(g_summed[i], g_sc2[c], g_sh2[c]));
        fout[i] = v;
        splitbf(v, g_AH[i], g_AL[i]);
    }
}

// ---------------- head -------------------------------------------------------
__global__ void head_k(const float* __restrict__ afea, const int* __restrict__ cai,
                       const float* __restrict__ Wfc, const float* __restrict__ bfc,
                       const float* __restrict__ Wout, const float* __restrict__ bout,
                       float* __restrict__ out) {
    __shared__ float scry[AFD];
    __shared__ float shid[HF];
    __shared__ float part[2][AFD];
    int b = blockIdx.x, t = threadIdx.x;
    int c = t & 63, h = t >> 6;

    const int* idx = cai + b * APC;
    float acc = 0;
    for (int a = h * (APC / 2); a < (h + 1) * (APC / 2); a++)
        acc += afea[idx[a] * AFD + c];
    part[h][c] = acc;
    __syncthreads();

    if (t < AFD) scry[t] = sftp((part[0][t] + part[1][t]) * (1.0f / (float)APC));
    __syncthreads();

    float a2 = bfc[t];
    for (int k = 0; k < AFD; k++) a2 = fmaf(scry[k], Wfc[k * HF + t], a2);
    shid[t] = sftp(a2);
    __syncthreads();

    if (t < HID) {
        float a3 = bout[t];
        for (int k = 0; k < HF; k++) a3 = fmaf(shid[k], Wout[k * HID + t], a3);
        out[b * HID + t] = a3;
    }
}

// ---------------- launch -----------------------------------------------------
extern "C" void kernel_launch(void* const* d_in, const int* in_sizes, int n_in,
                              void* d_out, int out_size) {
    const int*   atom_num = (const int*)d_in[0];
    const float* nbr_fea  = (const float*)d_in[1];
    const int*   nidx     = (const int*)d_in[2];
    const int*   cai      = (const int*)d_in[3];
    const float* emb      = (const float*)d_in[4];
    const float* W_full   = (const float*)d_in[5];
    const float* b_full   = (const float*)d_in[6];
    const float* bn1g     = (const float*)d_in[7];
    const float* bn1b     = (const float*)d_in[8];
    const float* bn2g     = (const float*)d_in[9];
    const float* bn2b     = (const float*)d_in[10];
    const float* Wfc      = (const float*)d_in[11];
    const float* bfc      = (const float*)d_in[12];
    const float* Wout     = (const float*)d_in[13];
    const float* bout     = (const float*)d_in[14];
    float* out = (float*)d_out;

    cudaFuncSetAttribute(convg,   cudaFuncAttributeMaxDynamicSharedMemorySize, SMEM_DYN);
    cudaFuncSetAttribute(selfg_k, cudaFuncAttributeMaxDynamicSharedMemorySize, SG_DYN);

    void *p0, *p1;
    cudaGetSymbolAddress(&p0, g_fea0);
    cudaGetSymbolAddress(&p1, g_fea1);
    float* fin  = (float*)p0;
    float* fout = (float*)p1;

    embed2_k<<<(NA * AFD + 255) / 256, 256>>>(atom_num, emb);
    nbrcvt_k<<<(NA * MM * NFP + 255) / 256, 256>>>(nbr_fea);

    for (int i = 0; i < NCONV; i++) {
        const float* Wlp = W_full + (size_t)i * KD * CD;
        const float* blp = b_full + (size_t)i * CD;
        selfg_k<<<(NA + 127) / 128, 512, SG_DYN>>>(Wlp, blp);
        convg<<<NBLK, 512, SMEM_DYN>>>(nidx, Wlp);
        fin1_k<<<1, 512>>>(bn1g + (size_t)i * CD, bn1b + (size_t)i * CD);
        pass2s_k<<<G2BLK, 256>>>();
        fin2_k<<<1, 512>>>(bn2g + (size_t)i * AFD, bn2b + (size_t)i * AFD);
        update_k<<<(NA * AFD + 255) / 256, 256>>>(fin, fout);
        float* tmp = fin; fin = fout; fout = tmp;
    }

    head_k<<<NCRY, 128>>>(fin, cai, Wfc, bfc, Wout, bout, out);
}

// round 13
// speedup vs baseline: 11.0025x; 1.2779x over previous
#include <cuda_runtime.h>
#include <cuda_bf16.h>
#include <cuda_fp16.h>
#include <cstdint>

#define NA   100000
#define MM   12
#define AFD  64
#define NFD  41
#define KD   169
#define CD   128
#define NCONV 3
#define NCRY 100
#define APC  1000
#define HF   128
#define HID  64
#define EPSV 1e-5f

#define NBLK   148
#define TATOMS 10
#define NTILES (NA / TATOMS)   // 10000
#define TROWS  120
#define KSTEPS 7               // K_rest = 112 (64 nbr + 48 bond-pad)
#define ASTRE  120
#define ASTRB  240
#define NFP    48

#define G2BLK  1184

// ---- convg SMEM byte offsets (from 1024-aligned base) ----
#define WHI_OFF   0u           // 128 ch x 120 k x 2B
#define WLO_OFF   30720u
#define A_OFF     61440u       // 2 stages x (hi 30720 | lo 30720 | self 5280+pad)
#define STG_B     66816u
#define SELF_IN   61440u       // self offset inside a stage
#define SIDX_OFF  195072u      // 2 x 128 i32
#define SMEM_USED 196096u
#define SMEM_DYN  (SMEM_USED + 1024u)
// stat-reduction overlays (reuse W/A region after mainloop)
#define SREDS_OFF 0u
#define SREDQ_OFF 16896u

// ---- selfg SMEM ----
#define SGA_HI  0u
#define SGA_LO  18432u
#define SGW_HI  36864u
#define SGW_LO  55296u
#define SGBIAS  73728u
#define SG_USED 74240u
#define SG_DYN  (SG_USED + 1024u)

typedef unsigned long long ull;

// ---------------- scratch (device globals) ----------------------------------
__device__ float g_fea0[NA * AFD];
__device__ float g_fea1[NA * AFD];
__device__ float g_summed[NA * AFD];
__device__ __half g_gated[NA * MM * CD];         // 307 MB fp16
__device__ float g_self[NA * CD];                // 205 MB fp32
__device__ __nv_bfloat16 g_AH[NA * AFD], g_AL[NA * AFD];
__device__ __nv_bfloat16 g_NH[NA * MM * NFP], g_NL[NA * MM * NFP];
__device__ float g_part1[NBLK * 2 * CD];
__device__ float g_part2[G2BLK * 2 * AFD];
__device__ float g_sc1[CD], g_sh1[CD];
__device__ float g_sc2[AFD], g_sh2[AFD];

// ---------------- helpers ----------------------------------------------------
__device__ __forceinline__ uint32_t smem_u32(const void* p) {
    uint32_t a;
    asm("{ .reg .u64 t; cvta.to.shared.u64 t, %1; cvt.u32.u64 %0, t; }"
        : "=r"(a) : "l"(p));
    return a;
}

#define LDSM4(r, addr) \
    asm volatile("ldmatrix.sync.aligned.m8n8.x4.shared.b16 {%0,%1,%2,%3},[%4];" \
        : "=r"((r)[0]), "=r"((r)[1]), "=r"((r)[2]), "=r"((r)[3]) : "r"(addr))

#define MMA16(c, a, b) \
    asm volatile("mma.sync.aligned.m16n8k16.row.col.f32.bf16.bf16.f32 " \
        "{%0,%1,%2,%3},{%4,%5,%6,%7},{%8,%9},{%0,%1,%2,%3};" \
        : "+f"((c)[0]), "+f"((c)[1]), "+f"((c)[2]), "+f"((c)[3]) \
        : "r"((a)[0]), "r"((a)[1]), "r"((a)[2]), "r"((a)[3]), \
          "r"((b)[0]), "r"((b)[1]))

#define CPA16(dst, src) \
    asm volatile("cp.async.cg.shared.global [%0],[%1],16;" \
        :: "r"(dst), "l"(src) : "memory")
#define CPA_COMMIT() asm volatile("cp.async.commit_group;" ::: "memory")
#define CPA_WAIT1()  asm volatile("cp.async.wait_group 1;" ::: "memory")

__device__ __forceinline__ void splitbf(float v, __nv_bfloat16& h, __nv_bfloat16& l) {
    h = __float2bfloat16(v);
    l = __float2bfloat16(v - __bfloat162float(h));
}
__device__ __forceinline__ float sigm(float x) {
    return __fdividef(1.0f, 1.0f + __expf(-x));
}
__device__ __forceinline__ float sftp(float x) {
    return fmaxf(x, 0.0f) + __logf(1.0f + __expf(-fabsf(x)));
}

// ---------------- embedding + bond preconversion -----------------------------
__global__ void embed2_k(const int* __restrict__ an, const float* __restrict__ emb) {
    int i = blockIdx.x * blockDim.x + threadIdx.x;
    if (i < NA * AFD) {
        int n = i >> 6, c = i & 63;
        float v = emb[an[n] * AFD + c];
        g_fea0[i] = v;
        splitbf(v, g_AH[i], g_AL[i]);
    }
}
__global__ void nbrcvt_k(const float* __restrict__ nbrf) {
    int i = blockIdx.x * blockDim.x + threadIdx.x;
    if (i < NA * MM * NFP) {
        int r = i / NFP, k = i - r * NFP;
        float v = (k < NFD) ? nbrf[r * NFD + k] : 0.0f;
        splitbf(v, g_NH[i], g_NL[i]);
    }
}

// ---------------- selfg: S = atom_fea @ W[0:64] + bias -----------------------
__global__ void __launch_bounds__(512, 1) selfg_k(
    const float* __restrict__ Wl, const float* __restrict__ bl)
{
    extern __shared__ char smraw[];
    char* base = (char*)((((uintptr_t)smraw) + 1023) & ~(uintptr_t)1023);
    const uint32_t bu = smem_u32(base);

    const int tid = threadIdx.x, wid = tid >> 5, lane = tid & 31;
    const int warp_m = wid & 3, warp_n = wid >> 2;
    const int R0 = warp_m * 32, N0 = warp_n * 32;
    const int n0 = blockIdx.x * 128;

    for (int i = tid; i < (int)(SG_USED / 4); i += 512) ((uint32_t*)base)[i] = 0;
    __syncthreads();

    for (int i = tid; i < 128 * 8; i += 512) {
        int r = i >> 3, c = i & 7;
        uint4 vh = make_uint4(0, 0, 0, 0), vl = make_uint4(0, 0, 0, 0);
        if (n0 + r < NA) {
            vh = *(const uint4*)((const char*)g_AH + (size_t)(n0 + r) * 128 + c * 16);
            vl = *(const uint4*)((const char*)g_AL + (size_t)(n0 + r) * 128 + c * 16);
        }
        *(uint4*)(base + SGA_HI + r * 144 + c * 16) = vh;
        *(uint4*)(base + SGA_LO + r * 144 + c * 16) = vl;
    }
    for (int i = tid; i < 64 * 128; i += 512) {
        int k = i >> 7, c = i & 127;
        __nv_bfloat16 h, l;
        splitbf(Wl[k * CD + c], h, l);
        *(__nv_bfloat16*)(base + SGW_HI + c * 144 + k * 2) = h;
        *(__nv_bfloat16*)(base + SGW_LO + c * 144 + k * 2) = l;
    }
    if (tid < 128) ((float*)(base + SGBIAS))[tid] = bl[tid];
    __syncthreads();

    const uint32_t aoffb = (uint32_t)(((R0 + (lane & 15)) * 72 + (lane >> 4) * 8) * 2);
    const uint32_t aH0 = bu + SGA_HI + aoffb, aH1 = aH0 + 16 * 144;
    const uint32_t aL0 = bu + SGA_LO + aoffb, aL1 = aL0 + 16 * 144;
    const uint32_t boffb = (uint32_t)(((N0 + (lane & 7) + (lane >> 4) * 8) * 72
                                      + ((lane >> 3) & 1) * 8) * 2);
    const uint32_t bH0 = bu + SGW_HI + boffb, bH1 = bH0 + 16 * 144;
    const uint32_t bL0 = bu + SGW_LO + boffb, bL1 = bL0 + 16 * 144;

    float bch[8];
#pragma unroll
    for (int j = 0; j < 4; j++) {
        bch[j * 2]     = ((float*)(base + SGBIAS))[N0 + j * 8 + (lane & 3) * 2];
        bch[j * 2 + 1] = ((float*)(base + SGBIAS))[N0 + j * 8 + (lane & 3) * 2 + 1];
    }

    float C[2][4][4];
#pragma unroll
    for (int mi = 0; mi < 2; mi++)
#pragma unroll
        for (int j = 0; j < 4; j++)
#pragma unroll
            for (int p = 0; p < 4; p++) C[mi][j][p] = 0.0f;

#pragma unroll
    for (int ks = 0; ks < 4; ks++) {
        const uint32_t ko = (uint32_t)ks * 32u;
        uint32_t ah0[4], ah1[4], al0[4], al1[4], whA[4], whB[4], wlA[4], wlB[4];
        LDSM4(ah0, aH0 + ko); LDSM4(ah1, aH1 + ko);
        LDSM4(whA, bH0 + ko); LDSM4(whB, bH1 + ko);
        MMA16(C[0][0], ah0, whA + 0); MMA16(C[0][1], ah0, whA + 2);
        MMA16(C[0][2], ah0, whB + 0); MMA16(C[0][3], ah0, whB + 2);
        MMA16(C[1][0], ah1, whA + 0); MMA16(C[1][1], ah1, whA + 2);
        MMA16(C[1][2], ah1, whB + 0); MMA16(C[1][3], ah1, whB + 2);
        LDSM4(wlA, bL0 + ko); LDSM4(wlB, bL1 + ko);
        MMA16(C[0][0], ah0, wlA + 0); MMA16(C[0][1], ah0, wlA + 2);
        MMA16(C[0][2], ah0, wlB + 0); MMA16(C[0][3], ah0, wlB + 2);
        MMA16(C[1][0], ah1, wlA + 0); MMA16(C[1][1], ah1, wlA + 2);
        MMA16(C[1][2], ah1, wlB + 0); MMA16(C[1][3], ah1, wlB + 2);
        LDSM4(al0, aL0 + ko); LDSM4(al1, aL1 + ko);
        MMA16(C[0][0], al0, whA + 0); MMA16(C[0][1], al0, whA + 2);
        MMA16(C[0][2], al0, whB + 0); MMA16(C[0][3], al0, whB + 2);
        MMA16(C[1][0], al1, whA + 0); MMA16(C[1][1], al1, whA + 2);
        MMA16(C[1][2], al1, whB + 0); MMA16(C[1][3], al1, whB + 2);
    }

#pragma unroll
    for (int mi = 0; mi < 2; mi++) {
        int r0 = R0 + mi * 16 + (lane >> 2);
        int r1 = r0 + 8;
#pragma unroll
        for (int j = 0; j < 4; j++) {
            int col = N0 + j * 8 + (lane & 3) * 2;
            if (n0 + r0 < NA)
                *(float2*)&g_self[(size_t)(n0 + r0) * CD + col] =
                    make_float2(C[mi][j][0] + bch[j * 2], C[mi][j][1] + bch[j * 2 + 1]);
            if (n0 + r1 < NA)
                *(float2*)&g_self[(size_t)(n0 + r1) * CD + col] =
                    make_float2(C[mi][j][2] + bch[j * 2], C[mi][j][3] + bch[j * 2 + 1]);
        }
    }
}

// ---------------- convg: rest-GEMM (K=112) + self add -> gated(fp16) + stats -
__global__ void __launch_bounds__(512, 1) convg(const int* __restrict__ nidx,
                                                const float* __restrict__ Wl)
{
    extern __shared__ char smraw[];
    char* base = (char*)((((uintptr_t)smraw) + 1023) & ~(uintptr_t)1023);
    const uint32_t bu = smem_u32(base);

    const int tid = threadIdx.x, wid = tid >> 5, lane = tid & 31;
    const int warp_m = wid & 3, warp_n = wid >> 2;
    const int R0 = warp_m * 32, N0 = warp_n * 32;
    int* sIdx = (int*)(base + SIDX_OFF);

    for (int i = tid; i < (int)(SMEM_USED / 4); i += 512) ((uint32_t*)base)[i] = 0;
    __syncthreads();

    // W^T hi/lo for k_global 64..168 (local 0..104; 105..111 stay zero)
    for (int i = tid; i < 105 * 128; i += 512) {
        int k = i >> 7, c = i & 127;
        __nv_bfloat16 h, l;
        splitbf(Wl[(64 + k) * CD + c], h, l);
        *(__nv_bfloat16*)(base + WHI_OFF + c * ASTRB + k * 2) = h;
        *(__nv_bfloat16*)(base + WLO_OFF + c * ASTRB + k * 2) = l;
    }

    int tile = blockIdx.x;
    if (tid < TROWS) sIdx[tid] = nidx[tile * TROWS + tid];
    __syncthreads();

    // staged: A hi/lo (cp.async) + self rows (cp.async, 528B/atom stagger)
    auto STAGE = [&](int t, int sbuf) {
        const int rbase = t * TROWS;
        const int a0 = t * TATOMS;
        const int* sx = sIdx + sbuf * 128;
        const uint32_t dH = bu + A_OFF + (uint32_t)sbuf * STG_B;
        const uint32_t dL = dH + 30720u;
        const uint32_t dS = dH + SELF_IN;
        for (int i = tid; i < TROWS * 14 + 320; i += 512) {
            if (i < TROWS * 14) {
                int r = i / 14, c = i - r * 14;
                const char *sh, *sl;
                uint32_t doff;
                if (c < 8) {
                    size_t off = (size_t)sx[r] * 128 + c * 16;
                    sh = (const char*)g_AH + off; sl = (const char*)g_AL + off;
                    doff = (uint32_t)(r * ASTRB + c * 16);
                } else {
                    size_t off = (size_t)(rbase + r) * 96 + (c - 8) * 16;
                    sh = (const char*)g_NH + off; sl = (const char*)g_NL + off;
                    doff = (uint32_t)(r * ASTRB + 128 + (c - 8) * 16);
                }
                CPA16(dH + doff, sh);
                CPA16(dL + doff, sl);
            } else {
                int idx = i - TROWS * 14;
                int a = idx >> 5, c = idx & 31;       // 32 x 16B chunks per atom
                CPA16(dS + (uint32_t)(a * 528 + c * 16),
                      (const char*)g_self + (size_t)(a0 + a) * 512 + c * 16);
            }
        }
    };

    STAGE(tile, 0);
    CPA_COMMIT();

    const uint32_t aoffb = (uint32_t)(((R0 + (lane & 15)) * ASTRE + (lane >> 4) * 8) * 2);
    const uint32_t boffb = (uint32_t)(((N0 + (lane & 7) + (lane >> 4) * 8) * ASTRE
                                      + ((lane >> 3) & 1) * 8) * 2);
    const uint32_t bH0 = bu + WHI_OFF + boffb, bH1 = bH0 + 16 * ASTRB;
    const uint32_t bL0 = bu + WLO_OFF + boffb, bL1 = bL0 + 16 * ASTRB;

    float sS[8], sQ[8];
#pragma unroll
    for (int j = 0; j < 8; j++) { sS[j] = 0.0f; sQ[j] = 0.0f; }

    for (int it = 0; tile < NTILES; it++, tile += NBLK) {
        const int nxt = tile + NBLK;
        const int sb = it & 1;

        if (nxt < NTILES && tid < TROWS)
            sIdx[(sb ^ 1) * 128 + tid] = nidx[nxt * TROWS + tid];
        __syncthreads();               // prev tile fully consumed; sIdx visible
        if (nxt < NTILES) STAGE(nxt, sb ^ 1);
        CPA_COMMIT();
        CPA_WAIT1();
        __syncthreads();

        const uint32_t AH = bu + A_OFF + (uint32_t)sb * STG_B;
        const uint32_t AL = AH + 30720u;
        const uint32_t aH0 = AH + aoffb, aH1 = aH0 + 16 * ASTRB;
        const uint32_t aL0 = AL + aoffb, aL1 = aL0 + 16 * ASTRB;
        const float* sSelf = (const float*)(base + A_OFF + (size_t)sb * STG_B + SELF_IN);

        float C[2][4][4];
#pragma unroll
        for (int mi = 0; mi < 2; mi++)
#pragma unroll
            for (int j = 0; j < 4; j++)
#pragma unroll
                for (int p = 0; p < 4; p++) C[mi][j][p] = 0.0f;

#pragma unroll
        for (int ks = 0; ks < KSTEPS; ks++) {
            const uint32_t ko = (uint32_t)ks * 32u;
            uint32_t ah0[4], ah1[4], al0[4], al1[4], whA[4], whB[4], wlA[4], wlB[4];
            LDSM4(ah0, aH0 + ko); LDSM4(ah1, aH1 + ko);
            LDSM4(whA, bH0 + ko); LDSM4(whB, bH1 + ko);
            MMA16(C[0][0], ah0, whA + 0); MMA16(C[0][1], ah0, whA + 2);
            MMA16(C[0][2], ah0, whB + 0); MMA16(C[0][3], ah0, whB + 2);
            MMA16(C[1][0], ah1, whA + 0); MMA16(C[1][1], ah1, whA + 2);
            MMA16(C[1][2], ah1, whB + 0); MMA16(C[1][3], ah1, whB + 2);
            LDSM4(wlA, bL0 + ko); LDSM4(wlB, bL1 + ko);
            MMA16(C[0][0], ah0, wlA + 0); MMA16(C[0][1], ah0, wlA + 2);
            MMA16(C[0][2], ah0, wlB + 0); MMA16(C[0][3], ah0, wlB + 2);
            MMA16(C[1][0], ah1, wlA + 0); MMA16(C[1][1], ah1, wlA + 2);
            MMA16(C[1][2], ah1, wlB + 0); MMA16(C[1][3], ah1, wlB + 2);
            LDSM4(al0, aL0 + ko); LDSM4(al1, aL1 + ko);
            MMA16(C[0][0], al0, whA + 0); MMA16(C[0][1], al0, whA + 2);
            MMA16(C[0][2], al0, whB + 0); MMA16(C[0][3], al0, whB + 2);
            MMA16(C[1][0], al1, whA + 0); MMA16(C[1][1], al1, whA + 2);
            MMA16(C[1][2], al1, whB + 0); MMA16(C[1][3], al1, whB + 2);
        }

        // ---- epilogue: + self (SMEM), store gated fp16, accumulate stats ----
        const int growb = tile * TROWS;
#pragma unroll
        for (int mi = 0; mi < 2; mi++) {
            const int r0 = R0 + mi * 16 + (lane >> 2);
            const int r1 = r0 + 8;
            const bool v1 = (r1 < TROWS);
            const int a0l = r0 / MM;
            const int a1l = r1 / MM;
#pragma unroll
            for (int j = 0; j < 4; j++) {
                const int col = N0 + j * 8 + (lane & 3) * 2;
                float2 s0 = *(const float2*)&sSelf[a0l * 132 + col];
                float g0 = C[mi][j][0] + s0.x;
                float g1 = C[mi][j][1] + s0.y;
                *(__half2*)&g_gated[(size_t)(growb + r0) * CD + col] =
                    __floats2half2_rn(g0, g1);
                sS[j * 2] += g0; sS[j * 2 + 1] += g1;
                sQ[j * 2] = fmaf(g0, g0, sQ[j * 2]);
                sQ[j * 2 + 1] = fmaf(g1, g1, sQ[j * 2 + 1]);
                if (v1) {
                    float2 s1 = *(const float2*)&sSelf[a1l * 132 + col];
                    float g2 = C[mi][j][2] + s1.x;
                    float g3 = C[mi][j][3] + s1.y;
                    *(__half2*)&g_gated[(size_t)(growb + r1) * CD + col] =
                        __floats2half2_rn(g2, g3);
                    sS[j * 2] += g2; sS[j * 2 + 1] += g3;
                    sQ[j * 2] = fmaf(g2, g2, sQ[j * 2]);
                    sQ[j * 2 + 1] = fmaf(g3, g3, sQ[j * 2 + 1]);
                }
            }
        }
    }

    // ---- deterministic per-block stat reduction (overlay W/A region) ----
    __syncthreads();
    {
        float* sredS = (float*)(base + SREDS_OFF);   // [128][33]
        float* sredQ = (float*)(base + SREDQ_OFF);
        const int idx = warp_m * 8 + (lane >> 2);
#pragma unroll
        for (int j = 0; j < 4; j++)
#pragma unroll
            for (int e = 0; e < 2; e++) {
                int c = N0 + j * 8 + (lane & 3) * 2 + e;
                sredS[c * 33 + idx] = sS[j * 2 + e];
                sredQ[c * 33 + idx] = sQ[j * 2 + e];
            }
        __syncthreads();
        if (tid < 256) {
            int stat = tid >> 7, c = tid & 127;
            const float* p = stat ? sredQ : sredS;
            float v = 0.0f;
#pragma unroll
            for (int w = 0; w < 32; w++) v += p[c * 33 + w];
            g_part1[blockIdx.x * 2 * CD + tid] = v;
        }
    }
}

// ---------------- streaming pass2 (fp16 gated in) ----------------------------
__global__ void __launch_bounds__(256) pass2s_k() {
    const int tid = threadIdx.x;
    const int o0 = blockIdx.x * 256 + tid;
    const int c = o0 & 63;
    const float scF = g_sc1[c],      shF = g_sh1[c];
    const float scC = g_sc1[64 + c], shC = g_sh1[64 + c];

    float ssum = 0.0f, ssq = 0.0f;
    for (int o = o0; o < NA * AFD; o += G2BLK * 256) {
        const int n = o >> 6;
        const __half* gp = g_gated + (size_t)n * (MM * CD);
        float s = 0.0f;
#pragma unroll
        for (int m = 0; m < MM; m++) {
            float f  = fmaf(__half2float(gp[m * CD + c]),      scF, shF);
            float co = fmaf(__half2float(gp[m * CD + 64 + c]), scC, shC);
            s += sigm(f) * sftp(co);
        }
        g_summed[o] = s;
        ssum += s; ssq = fmaf(s, s, ssq);
    }

    __shared__ float sr[512];
    sr[tid] = ssum; sr[256 + tid] = ssq;
    __syncthreads();
    if (tid < 128) {
        int st = tid >> 6, cc = tid & 63;
        const float* b = sr + st * 256;
        g_part2[blockIdx.x * 128 + tid] = b[cc] + b[cc + 64] + b[cc + 128] + b[cc + 192];
    }
}

// ---------------- BN finalize ------------------------------------------------
__global__ void __launch_bounds__(512) fin1_k(const float* __restrict__ g,
                                              const float* __restrict__ b) {
    __shared__ float sm[2][512];
    int tid = threadIdx.x, c = tid & 127, grp = tid >> 7;
    float s = 0, q = 0;
    for (int bl = grp; bl < NBLK; bl += 4) {
        s += g_part1[bl * 2 * CD + c];
        q += g_part1[bl * 2 * CD + CD + c];
    }
    sm[0][tid] = s; sm[1][tid] = q;
    __syncthreads();
    if (tid < 128) {
        float S = sm[0][tid] + sm[0][128 + tid] + sm[0][256 + tid] + sm[0][384 + tid];
        float Q = sm[1][tid] + sm[1][128 + tid] + sm[1][256 + tid] + sm[1][384 + tid];
        const float inv = 1.0f / ((float)NA * (float)MM);
        float mu = S * inv;
        float var = Q * inv - mu * mu;
        float sc = g[tid] * rsqrtf(var + EPSV);
        g_sc1[tid] = sc;
        g_sh1[tid] = b[tid] - mu * sc;
    }
}
__global__ void __launch_bounds__(512) fin2_k(const float* __restrict__ g,
                                              const float* __restrict__ b) {
    __shared__ float sm[2][512];
    int tid = threadIdx.x, c = tid & 63, grp = tid >> 6;
    float s = 0, q = 0;
    for (int bl = grp; bl < G2BLK; bl += 8) {
        s += g_part2[bl * 128 + c];
        q += g_part2[bl * 128 + 64 + c];
    }
    sm[0][tid] = s; sm[1][tid] = q;
    __syncthreads();
    if (tid < 64) {
        float S = 0, Q = 0;
#pragma unroll
        for (int w = 0; w < 8; w++) { S += sm[0][w * 64 + tid]; Q += sm[1][w * 64 + tid]; }
        const float inv = 1.0f / (float)NA;
        float mu = S * inv;
        float var = Q * inv - mu * mu;
        float sc = g[tid] * rsqrtf(var + EPSV);
        g_sc2[tid] = sc;
        g_sh2[tid] = b[tid] - mu * sc;
    }
}

// ---------------- residual + bn2 + softplus (+ bf16 hi/lo) -------------------
__global__ void update_k(const float* __restrict__ fin, float* __restrict__ fout) {
    int i = blockIdx.x * blockDim.x + threadIdx.x;
    if (i < NA * AFD) {
        int c = i & 63;
        float v = sftp(fin[i] + fmaf(g_summed[i], g_sc2[c], g_sh2[c]));
        fout[i] = v;
        splitbf(v, g_AH[i], g_AL[i]);
    }
}

// ---------------- head -------------------------------------------------------
__global__ void head_k(const float* __restrict__ afea, const int* __restrict__ cai,
                       const float* __restrict__ Wfc, const float* __restrict__ bfc,
                       const float* __restrict__ Wout, const float* __restrict__ bout,
                       float* __restrict__ out) {
    __shared__ float scry[AFD];
    __shared__ float shid[HF];
    __shared__ float part[2][AFD];
    int b = blockIdx.x, t = threadIdx.x;
    int c = t & 63, h = t >> 6;

    const int* idx = cai + b * APC;
    float acc = 0;
    for (int a = h * (APC / 2); a < (h + 1) * (APC / 2); a++)
        acc += afea[idx[a] * AFD + c];
    part[h][c] = acc;
    __syncthreads();

    if (t < AFD) scry[t] = sftp((part[0][t] + part[1][t]) * (1.0f / (float)APC));
    __syncthreads();

    float a2 = bfc[t];
    for (int k = 0; k < AFD; k++) a2 = fmaf(scry[k], Wfc[k * HF + t], a2);
    shid[t] = sftp(a2);
    __syncthreads();

    if (t < HID) {
        float a3 = bout[t];
        for (int k = 0; k < HF; k++) a3 = fmaf(shid[k], Wout[k * HID + t], a3);
        out[b * HID + t] = a3;
    }
}

// ---------------- launch -----------------------------------------------------
extern "C" void kernel_launch(void* const* d_in, const int* in_sizes, int n_in,
                              void* d_out, int out_size) {
    const int*   atom_num = (const int*)d_in[0];
    const float* nbr_fea  = (const float*)d_in[1];
    const int*   nidx     = (const int*)d_in[2];
    const int*   cai      = (const int*)d_in[3];
    const float* emb      = (const float*)d_in[4];
    const float* W_full   = (const float*)d_in[5];
    const float* b_full   = (const float*)d_in[6];
    const float* bn1g     = (const float*)d_in[7];
    const float* bn1b     = (const float*)d_in[8];
    const float* bn2g     = (const float*)d_in[9];
    const float* bn2b     = (const float*)d_in[10];
    const float* Wfc      = (const float*)d_in[11];
    const float* bfc      = (const float*)d_in[12];
    const float* Wout     = (const float*)d_in[13];
    const float* bout     = (const float*)d_in[14];
    float* out = (float*)d_out;

    cudaFuncSetAttribute(convg,   cudaFuncAttributeMaxDynamicSharedMemorySize, SMEM_DYN);
    cudaFuncSetAttribute(selfg_k, cudaFuncAttributeMaxDynamicSharedMemorySize, SG_DYN);

    void *p0, *p1;
    cudaGetSymbolAddress(&p0, g_fea0);
    cudaGetSymbolAddress(&p1, g_fea1);
    float* fin  = (float*)p0;
    float* fout = (float*)p1;

    embed2_k<<<(NA * AFD + 255) / 256, 256>>>(atom_num, emb);
    nbrcvt_k<<<(NA * MM * NFP + 255) / 256, 256>>>(nbr_fea);

    for (int i = 0; i < NCONV; i++) {
        const float* Wlp = W_full + (size_t)i * KD * CD;
        const float* blp = b_full + (size_t)i * CD;
        selfg_k<<<(NA + 127) / 128, 512, SG_DYN>>>(Wlp, blp);
        convg<<<NBLK, 512, SMEM_DYN>>>(nidx, Wlp);
        fin1_k<<<1, 512>>>(bn1g + (size_t)i * CD, bn1b + (size_t)i * CD);
        pass2s_k<<<G2BLK, 256>>>();
        fin2_k<<<1, 512>>>(bn2g + (size_t)i * AFD, bn2b + (size_t)i * AFD);
        update_k<<<(NA * AFD + 255) / 256, 256>>>(fin, fout);
        float* tmp = fin; fin = fout; fout = tmp;
    }

    head_k<<<NCRY, 128>>>(fin, cai, Wfc, bfc, Wout, bout, out);
}